// round 3
// baseline (speedup 1.0000x reference)
#include <cuda_runtime.h>
#include <math.h>

#define BB   256
#define TT   128
#define LL   64
#define EENC 512
#define DD   512
#define EMBW 128
#define AA   129
#define ATTH 20

// ---------------- device scratch (static, no allocs) ----------------
__device__ __align__(16) float g_eseq[TT * BB * EMBW];
__device__ __align__(16) float g_encatt[BB * LL * ATTH];
__device__ __align__(16) float g_att[BB * DD];
__device__ __align__(16) float g_h[3][2][BB * DD];
__device__ __align__(16) float g_c[3][BB * DD];
__device__ __align__(16) float g_ctx[BB * EENC];
__device__ __align__(16) float g_act1[BB * DD];

__device__ unsigned int g_bar_count = 0;
__device__ unsigned int g_bar_gen   = 0;

// ---------------- packed f32x2 helpers ----------------
__device__ __forceinline__ unsigned long long dup2(float x) {
    unsigned long long r;
    asm("mov.b64 %0, {%1, %1};" : "=l"(r) : "f"(x));
    return r;
}
__device__ __forceinline__ void fma2(unsigned long long& d,
                                     unsigned long long a, unsigned long long b) {
    asm("fma.rn.f32x2 %0, %1, %2, %0;" : "+l"(d) : "l"(a), "l"(b));
}
__device__ __forceinline__ float2 unpack2(unsigned long long v) {
    float2 r;
    asm("mov.b64 {%0, %1}, %2;" : "=f"(r.x), "=f"(r.y) : "l"(v));
    return r;
}

// ---------------- launch-reentrant grid barrier ----------------
__device__ __forceinline__ void gsync(int nb) {
    __syncthreads();
    if (threadIdx.x == 0) {
        __threadfence();
        unsigned int gen = *(volatile unsigned int*)&g_bar_gen;
        if (atomicAdd(&g_bar_count, 1u) == (unsigned int)(nb - 1)) {
            g_bar_count = 0;
            __threadfence();
            atomicAdd(&g_bar_gen, 1u);
        } else {
            while (*(volatile unsigned int*)&g_bar_gen == gen) { }
        }
        __threadfence();
    }
    __syncthreads();
}

// ---------------- 32x32 cat-GEMM tile:  C = [A1|A2] @ W^T + bias ----------------
// W is a single [N, K1+K2] row-major matrix (concat only on the A side).
__device__ __forceinline__ void gemm32_tile(
    float* sm, int tile,
    const float* __restrict__ A1, int K1,
    const float* __restrict__ A2, int K2,
    const float* __restrict__ W, int ldw,
    const float* __restrict__ bias,
    float* __restrict__ C, size_t ldc, int N, int relu)
{
    __syncthreads();                       // protect smem from previous user
    const int tid = threadIdx.x;
    const int ntN = (N + 31) >> 5;
    const int m0 = (tile / ntN) * 32;
    const int n0 = (tile % ntN) * 32;
    float* As = sm;                        // [16][36]
    float* Ws = sm + 16 * 36;              // [16][36]
    const int tn = tid & 15, tm = tid >> 4; // 16x16 threads, TM=TN=2
    unsigned long long acc0 = 0ull, acc1 = 0ull;
    const int K = K1 + K2;

    for (int k0 = 0; k0 < K; k0 += 16) {
        if (tid < 128) {
            const float* A; int lda, kb;
            if (k0 < K1) { A = A1; lda = K1; kb = k0; }
            else         { A = A2; lda = K2; kb = k0 - K1; }
            int m = tid >> 2, kq = tid & 3;
            float4 v = *(const float4*)(A + (size_t)(m0 + m) * lda + kb + kq * 4);
            As[(kq * 4 + 0) * 36 + m] = v.x; As[(kq * 4 + 1) * 36 + m] = v.y;
            As[(kq * 4 + 2) * 36 + m] = v.z; As[(kq * 4 + 3) * 36 + m] = v.w;
        } else {
            int i = tid - 128;
            int n = i >> 2, kq = i & 3;
            float4 v = make_float4(0.f, 0.f, 0.f, 0.f);
            if (n0 + n < N)
                v = *(const float4*)(W + (size_t)(n0 + n) * ldw + k0 + kq * 4);
            Ws[(kq * 4 + 0) * 36 + n] = v.x; Ws[(kq * 4 + 1) * 36 + n] = v.y;
            Ws[(kq * 4 + 2) * 36 + n] = v.z; Ws[(kq * 4 + 3) * 36 + n] = v.w;
        }
        __syncthreads();
#pragma unroll
        for (int k = 0; k < 16; k++) {
            float a0 = As[k * 36 + tm * 2];
            float a1 = As[k * 36 + tm * 2 + 1];
            unsigned long long w = *(const unsigned long long*)(Ws + k * 36 + tn * 2);
            fma2(acc0, dup2(a0), w);
            fma2(acc1, dup2(a1), w);
        }
        __syncthreads();
    }

    float2 p0 = unpack2(acc0);
    float2 p1 = unpack2(acc1);
    int n_a = n0 + tn * 2, n_b = n_a + 1;
    int m_a = m0 + tm * 2, m_b = m_a + 1;
    if (n_a < N) {
        float v0 = p0.x + bias[n_a];
        float v1 = p1.x + bias[n_a];
        if (relu) { v0 = fmaxf(v0, 0.f); v1 = fmaxf(v1, 0.f); }
        C[(size_t)m_a * ldc + n_a] = v0;
        C[(size_t)m_b * ldc + n_a] = v1;
    }
    if (n_b < N) {
        float v0 = p0.y + bias[n_b];
        float v1 = p1.y + bias[n_b];
        if (relu) { v0 = fmaxf(v0, 0.f); v1 = fmaxf(v1, 0.f); }
        C[(size_t)m_a * ldc + n_b] = v0;
        C[(size_t)m_b * ldc + n_b] = v1;
    }
}

// ---------------- LSTM 64x64 tile with fused gate pointwise ----------------
// N-tile ct covers d in [ct*16, ct*16+16) for ALL 4 gates (W-row remap), so the
// epilogue can compute c/h updates for its (64 m x 16 d) patch in-block.
__device__ __forceinline__ void lstm_tile(
    float* sm, int tile,
    const float* __restrict__ x, const float* __restrict__ hin,
    const float* __restrict__ Wih, const float* __restrict__ Whh,
    const float* __restrict__ bih, const float* __restrict__ bhh,
    float* __restrict__ hout, float* __restrict__ cbuf)
{
    __syncthreads();
    const int tid = threadIdx.x;
    const int m0 = (tile >> 5) * 64;
    const int d0 = (tile & 31) * 16;
    float* As = sm;                       // [16][68]
    float* Ws = sm + 16 * 68;             // [16][68]
    const int tn = tid & 15, tm = tid >> 4;  // 16x16, TM=TN=4

    unsigned long long acc[4][2];
#pragma unroll
    for (int im = 0; im < 4; im++) { acc[im][0] = 0ull; acc[im][1] = 0ull; }

    const int am = tid >> 2, akq = tid & 3;          // A staging role
    const int wj = tid >> 2, wkq = tid & 3;          // W staging role
    const int wrow = ((wj >> 4) << 9) + d0 + (wj & 15);  // gate*512 + d

    for (int k0 = 0; k0 < 1024; k0 += 16) {
        const float* A = (k0 < 512) ? x : hin;
        const float* W = (k0 < 512) ? Wih : Whh;
        int kb = k0 & 511;
        {
            float4 v = *(const float4*)(A + (size_t)(m0 + am) * 512 + kb + akq * 4);
            As[(akq * 4 + 0) * 68 + am] = v.x; As[(akq * 4 + 1) * 68 + am] = v.y;
            As[(akq * 4 + 2) * 68 + am] = v.z; As[(akq * 4 + 3) * 68 + am] = v.w;
            float4 w = *(const float4*)(W + (size_t)wrow * 512 + kb + wkq * 4);
            Ws[(wkq * 4 + 0) * 68 + wj] = w.x; Ws[(wkq * 4 + 1) * 68 + wj] = w.y;
            Ws[(wkq * 4 + 2) * 68 + wj] = w.z; Ws[(wkq * 4 + 3) * 68 + wj] = w.w;
        }
        __syncthreads();
#pragma unroll
        for (int k = 0; k < 16; k++) {
            const float* ar = As + k * 68 + tm * 4;
            unsigned long long w0 = *(const unsigned long long*)(Ws + k * 68 + tn * 4);
            unsigned long long w1 = *(const unsigned long long*)(Ws + k * 68 + tn * 4 + 2);
#pragma unroll
            for (int im = 0; im < 4; im++) {
                unsigned long long a2 = dup2(ar[im]);
                fma2(acc[im][0], a2, w0);
                fma2(acc[im][1], a2, w1);
            }
        }
        __syncthreads();
    }

    // epilogue: dump tile to smem [64][66], then pointwise LSTM update
    float* G = sm;   // reuse (all staged data consumed)
#pragma unroll
    for (int im = 0; im < 4; im++) {
        int m = tm * 4 + im;
        float2 p0 = unpack2(acc[im][0]);
        float2 p1 = unpack2(acc[im][1]);
        *(float2*)(G + m * 66 + tn * 4)     = p0;
        *(float2*)(G + m * 66 + tn * 4 + 2) = p1;
    }
    __syncthreads();

    for (int e = tid; e < 1024; e += 256) {
        int m = e & 63, dp = e >> 6;
        int d = d0 + dp;
        float gi = G[m * 66 + dp]      + bih[d]          + bhh[d];
        float gf = G[m * 66 + 16 + dp] + bih[512 + d]    + bhh[512 + d];
        float gg = G[m * 66 + 32 + dp] + bih[1024 + d]   + bhh[1024 + d];
        float go = G[m * 66 + 48 + dp] + bih[1536 + d]   + bhh[1536 + d];
        int row = m0 + m;
        float si = 1.f / (1.f + expf(-gi));
        float sf = 1.f / (1.f + expf(-gf));
        float so = 1.f / (1.f + expf(-go));
        float cn = sf * cbuf[(size_t)row * 512 + d] + si * tanhf(gg);
        cbuf[(size_t)row * 512 + d] = cn;
        hout[(size_t)row * 512 + d] = so * tanhf(cn);
    }
}

// ---------------- attention for one batch row ----------------
__device__ __forceinline__ void attention_row(
    float* sm, int b, const float* __restrict__ h2,
    const float* __restrict__ enc, const float* __restrict__ encatt,
    const float* __restrict__ Wa1, const float* __restrict__ Wa2,
    const float* __restrict__ ba2, float* __restrict__ ctx)
{
    __syncthreads();
    float* sh_h  = sm;
    float* sh_hp = sm + 512;
    float* sh_s  = sm + 544;
    int tid = threadIdx.x;

    for (int k = tid; k < DD; k += 256) sh_h[k] = h2[(size_t)b * DD + k];
    __syncthreads();

    int warp = tid >> 5, lane = tid & 31;
    for (int j = warp; j < ATTH; j += 8) {
        const float* w = Wa1 + (size_t)j * (EENC + DD) + EENC;
        float s = 0.f;
        for (int k = lane; k < DD; k += 32) s += sh_h[k] * w[k];
#pragma unroll
        for (int o = 16; o; o >>= 1) s += __shfl_xor_sync(0xFFFFFFFFu, s, o);
        if (lane == 0) sh_hp[j] = s;
    }
    __syncthreads();

    if (tid < LL) {
        const float* ea = encatt + ((size_t)b * LL + tid) * ATTH;
        float s = 0.f;
#pragma unroll
        for (int j = 0; j < ATTH; j++) {
            float v = ea[j] + sh_hp[j];
            v = v > 0.f ? v : 0.f;
            s += v * Wa2[j];
        }
        sh_s[tid] = tanhf(s + ba2[0]);
    }
    __syncthreads();

    if (tid == 0) {
        float m = sh_s[0];
        for (int l = 1; l < LL; l++) m = fmaxf(m, sh_s[l]);
        float sum = 0.f;
        for (int l = 0; l < LL; l++) { float e = expf(sh_s[l] - m); sh_s[l] = e; sum += e; }
        float inv = 1.f / sum;
        for (int l = 0; l < LL; l++) sh_s[l] *= inv;
    }
    __syncthreads();

    const float* eb = enc + (size_t)b * LL * EENC;
    for (int k = tid; k < EENC; k += 256) {
        float s = 0.f;
#pragma unroll 8
        for (int l = 0; l < LL; l++) s += sh_s[l] * eb[(size_t)l * EENC + k];
        ctx[(size_t)b * EENC + k] = s;
    }
}

// ---------------- kernel params ----------------
struct Params {
    const int* act;
    const float* enc;
    const float* enc_h;
    const float* enc_c;
    const float* embW;
    const float* Wc;  const float* bc;
    const float* Wih[3]; const float* Whh[3];
    const float* bih[3]; const float* bhh[3];
    const float* Wa1; const float* ba1;
    const float* Wa2; const float* ba2;
    const float* Wl1; const float* bl1;
    const float* Wl2; const float* bl2;
    float* out;
};

// ---------------- persistent mega-kernel ----------------
__global__ void __launch_bounds__(256, 1) decoder_kernel(Params p)
{
    __shared__ __align__(16) float sm[4352];
    const int nb  = gridDim.x;
    const int bid = blockIdx.x;
    const int tid = threadIdx.x;

    // ---- phase 0: setup ----
    for (int idx = bid * 256 + tid; idx < BB * DD; idx += nb * 256) {
        float h = p.enc_h[idx], c = p.enc_c[idx];
        g_h[0][0][idx] = h; g_h[1][0][idx] = h; g_h[2][0][idx] = h;
        g_c[0][idx] = c; g_c[1][idx] = c; g_c[2][idx] = c;
        g_ctx[idx] = 0.f;
    }
    for (int i4 = bid * 256 + tid; i4 < TT * BB * EMBW / 4; i4 += nb * 256) {
        int row = i4 >> 5;
        int kq  = i4 & 31;
        int t = row >> 8;
        int b = row & 255;
        float4 v = make_float4(0.f, 0.f, 0.f, 0.f);
        if (t > 0) {
            int a = p.act[b * TT + t - 1];
            v = *(const float4*)(p.embW + (size_t)a * EMBW + kq * 4);
        }
        *(float4*)(g_eseq + (size_t)row * EMBW + kq * 4) = v;
    }
    {
        int lane = tid & 31;
        int gw0 = (bid * 256 + tid) >> 5;
        for (int gw = gw0; gw < BB * LL; gw += nb * 8) {
            const float* er = p.enc + (size_t)gw * EENC;
            float r[16];
#pragma unroll
            for (int i = 0; i < 16; i++) r[i] = er[lane + 32 * i];
            for (int j = 0; j < ATTH; j++) {
                const float* w = p.Wa1 + (size_t)j * (EENC + DD);
                float s = 0.f;
#pragma unroll
                for (int i = 0; i < 16; i++) s += r[i] * w[lane + 32 * i];
#pragma unroll
                for (int o = 16; o; o >>= 1) s += __shfl_xor_sync(0xFFFFFFFFu, s, o);
                if (lane == 0) g_encatt[(size_t)gw * ATTH + j] = s + p.ba1[j];
            }
        }
    }
    gsync(nb);

    // ---- P1 for t=0: att = [e_0 | ctx0] @ Wc^T + bc ----
    for (int tile = bid; tile < 128; tile += nb)
        gemm32_tile(sm, tile, g_eseq, EMBW, g_ctx, EENC,
                    p.Wc, EMBW + EENC, p.bc, g_att, DD, DD, 0);
    gsync(nb);

    // ---- main loop ----
    for (int t = 0; t < TT; t++) {
        const int cur = t & 1, nxt = cur ^ 1;

        // 3 LSTM cells (gemm + fused pointwise)
        const float* xin = g_att;
        for (int cell = 0; cell < 3; cell++) {
            for (int tile = bid; tile < 128; tile += nb)
                lstm_tile(sm, tile, xin, g_h[cell][cur],
                          p.Wih[cell], p.Whh[cell], p.bih[cell], p.bhh[cell],
                          g_h[cell][nxt], g_c[cell]);
            gsync(nb);
            xin = g_h[cell][nxt];
        }

        // attention -> ctx
        for (int b = bid; b < BB; b += nb)
            attention_row(sm, b, g_h[2][nxt], p.enc, g_encatt,
                          p.Wa1, p.Wa2, p.ba2, g_ctx);
        gsync(nb);

        // action head L1: relu([h2|ctx] @ Wl1^T + bl1)
        for (int tile = bid; tile < 128; tile += nb)
            gemm32_tile(sm, tile, g_h[2][nxt], DD, g_ctx, EENC,
                        p.Wl1, DD + EENC, p.bl1, g_act1, DD, DD, 1);
        gsync(nb);

        // combined: logits(t) -> out  AND  att(t+1) (independent)
        const int ntot = 40 + ((t + 1 < TT) ? 128 : 0);
        for (int u = bid; u < ntot; u += nb) {
            if (u < 40)
                gemm32_tile(sm, u, g_act1, DD, (const float*)0, 0,
                            p.Wl2, DD, p.bl2,
                            p.out + (size_t)t * AA, (size_t)TT * AA, AA, 0);
            else
                gemm32_tile(sm, u - 40,
                            g_eseq + (size_t)(t + 1) * BB * EMBW, EMBW, g_ctx, EENC,
                            p.Wc, EMBW + EENC, p.bc, g_att, DD, DD, 0);
        }
        gsync(nb);
    }
}

// ---------------- host ----------------
extern "C" void kernel_launch(void* const* d_in, const int* in_sizes, int n_in,
                              void* d_out, int out_size)
{
    Params p;
    p.act    = (const int*)  d_in[0];
    p.enc    = (const float*)d_in[1];
    p.enc_h  = (const float*)d_in[2];
    p.enc_c  = (const float*)d_in[3];
    p.embW   = (const float*)d_in[4];
    p.Wc     = (const float*)d_in[5];
    p.bc     = (const float*)d_in[6];
    p.Wih[0] = (const float*)d_in[7];  p.Whh[0] = (const float*)d_in[8];
    p.bih[0] = (const float*)d_in[9];  p.bhh[0] = (const float*)d_in[10];
    p.Wih[1] = (const float*)d_in[11]; p.Whh[1] = (const float*)d_in[12];
    p.bih[1] = (const float*)d_in[13]; p.bhh[1] = (const float*)d_in[14];
    p.Wih[2] = (const float*)d_in[15]; p.Whh[2] = (const float*)d_in[16];
    p.bih[2] = (const float*)d_in[17]; p.bhh[2] = (const float*)d_in[18];
    p.Wa1 = (const float*)d_in[19]; p.ba1 = (const float*)d_in[20];
    p.Wa2 = (const float*)d_in[21]; p.ba2 = (const float*)d_in[22];
    p.Wl1 = (const float*)d_in[23]; p.bl1 = (const float*)d_in[24];
    p.Wl2 = (const float*)d_in[25]; p.bl2 = (const float*)d_in[26];
    p.out = (float*)d_out;

    int dev = 0;
    cudaGetDevice(&dev);
    int nsm = 0;
    cudaDeviceGetAttribute(&nsm, cudaDevAttrMultiProcessorCount, dev);
    if (nsm <= 0) nsm = 148;

    decoder_kernel<<<nsm, 256>>>(p);
}

// round 4
// speedup vs baseline: 1.1097x; 1.1097x over previous
#include <cuda_runtime.h>
#include <math.h>

#define BB   256
#define TT   128
#define LL   64
#define EENC 512
#define DD   512
#define EMBW 128
#define AA   129
#define ATTH 20

typedef unsigned long long ull;

// ---------------- device scratch (static, no allocs) ----------------
__device__ __align__(16) float g_eseq[TT * BB * EMBW];
__device__ __align__(16) float g_encatt[BB * LL * ATTH];
__device__ __align__(16) float g_att[BB * DD];
__device__ __align__(16) float g_h[3][2][BB * DD];
__device__ __align__(16) float g_c[3][BB * DD];
__device__ __align__(16) float g_ctx[BB * EENC];
__device__ __align__(16) float g_act1[BB * DD];

__device__ unsigned int g_bar_count = 0;
__device__ unsigned int g_bar_gen   = 0;

// ---------------- packed f32x2 helpers ----------------
__device__ __forceinline__ ull dup2(float x) {
    ull r;
    asm("mov.b64 %0, {%1, %1};" : "=l"(r) : "f"(x));
    return r;
}
__device__ __forceinline__ void fma2(ull& d, ull a, ull b) {
    asm("fma.rn.f32x2 %0, %1, %2, %0;" : "+l"(d) : "l"(a), "l"(b));
}
__device__ __forceinline__ float2 unpack2(ull v) {
    float2 r;
    asm("mov.b64 {%0, %1}, %2;" : "=f"(r.x), "=f"(r.y) : "l"(v));
    return r;
}

// ---------------- launch-reentrant grid barrier ----------------
__device__ __forceinline__ void gsync(int nb) {
    __syncthreads();
    if (threadIdx.x == 0) {
        __threadfence();
        unsigned int gen = *(volatile unsigned int*)&g_bar_gen;
        if (atomicAdd(&g_bar_count, 1u) == (unsigned int)(nb - 1)) {
            g_bar_count = 0;
            __threadfence();
            atomicAdd(&g_bar_gen, 1u);
        } else {
            while (*(volatile unsigned int*)&g_bar_gen == gen) { }
        }
        __threadfence();
    }
    __syncthreads();
}

// ---------------- 32x32 cat-GEMM tile (double-buffered, BK=16) ----------------
// C = [A1|A2] @ W^T + bias ; W is one [N, K1+K2] row-major matrix.
__device__ __forceinline__ void gemm32_tile(
    float* sm, int tile,
    const float* __restrict__ A1, int K1,
    const float* __restrict__ A2, int K2,
    const float* __restrict__ W, int ldw,
    const float* __restrict__ bias,
    float* __restrict__ C, size_t ldc, int N, int relu)
{
    __syncthreads();
    const int tid = threadIdx.x;
    const int ntN = (N + 31) >> 5;
    const int m0 = (tile / ntN) * 32;
    const int n0 = (tile % ntN) * 32;
    const int BUF = 16 * 36;                 // one As or Ws buffer
    const int tn = tid & 15, tm = tid >> 4;
    ull acc0 = 0ull, acc1 = 0ull;
    const int K = K1 + K2;
    const int nk = K >> 4;

    const bool isA = tid < 128;
    const int srow = (tid & 127) >> 2;       // 0..31
    const int skq  = (tid & 3) * 4;          // 0,4,8,12

    float4 v;
    {   // prefetch block 0
        if (isA) {
            const float* A; int lda, kb;
            if (K1 > 0) { A = A1; lda = K1; kb = 0; }
            else        { A = A2; lda = K2; kb = 0; }
            v = *(const float4*)(A + (size_t)(m0 + srow) * lda + kb + skq);
        } else {
            v = make_float4(0.f, 0.f, 0.f, 0.f);
            if (n0 + srow < N)
                v = *(const float4*)(W + (size_t)(n0 + srow) * ldw + skq);
        }
    }

    for (int i = 0; i < nk; i++) {
        float* as = sm + (i & 1) * (2 * BUF);
        float* ws = as + BUF;
        float* dst = isA ? as : ws;
        dst[(skq + 0) * 36 + srow] = v.x;
        dst[(skq + 1) * 36 + srow] = v.y;
        dst[(skq + 2) * 36 + srow] = v.z;
        dst[(skq + 3) * 36 + srow] = v.w;
        __syncthreads();
        if (i + 1 < nk) {
            int k0 = (i + 1) << 4;
            if (isA) {
                const float* A; int lda, kb;
                if (k0 < K1) { A = A1; lda = K1; kb = k0; }
                else         { A = A2; lda = K2; kb = k0 - K1; }
                v = *(const float4*)(A + (size_t)(m0 + srow) * lda + kb + skq);
            } else {
                v = make_float4(0.f, 0.f, 0.f, 0.f);
                if (n0 + srow < N)
                    v = *(const float4*)(W + (size_t)(n0 + srow) * ldw + k0 + skq);
            }
        }
#pragma unroll
        for (int k = 0; k < 16; k++) {
            float2 a2 = *(const float2*)(as + k * 36 + tm * 2);
            ull wv = *(const ull*)(ws + k * 36 + tn * 2);
            fma2(acc0, dup2(a2.x), wv);
            fma2(acc1, dup2(a2.y), wv);
        }
    }

    float2 p0 = unpack2(acc0);
    float2 p1 = unpack2(acc1);
    int n_a = n0 + tn * 2, n_b = n_a + 1;
    int m_a = m0 + tm * 2, m_b = m_a + 1;
    if (n_a < N) {
        float v0 = p0.x + bias[n_a];
        float v1 = p1.x + bias[n_a];
        if (relu) { v0 = fmaxf(v0, 0.f); v1 = fmaxf(v1, 0.f); }
        C[(size_t)m_a * ldc + n_a] = v0;
        C[(size_t)m_b * ldc + n_a] = v1;
    }
    if (n_b < N) {
        float v0 = p0.y + bias[n_b];
        float v1 = p1.y + bias[n_b];
        if (relu) { v0 = fmaxf(v0, 0.f); v1 = fmaxf(v1, 0.f); }
        C[(size_t)m_a * ldc + n_b] = v0;
        C[(size_t)m_b * ldc + n_b] = v1;
    }
}

// ---------------- LSTM 64x64 tile (double-buffered, BK=32, fused pointwise) ----
// N-tile covers d in [d0, d0+16) for ALL 4 gates via W-row remap.
__device__ __forceinline__ void lstm_tile(
    float* sm, int tile,
    const float* __restrict__ x, const float* __restrict__ hin,
    const float* __restrict__ Wih, const float* __restrict__ Whh,
    const float* __restrict__ bih, const float* __restrict__ bhh,
    float* __restrict__ hout, float* __restrict__ cbuf)
{
    __syncthreads();
    const int tid = threadIdx.x;
    const int m0 = (tile >> 5) * 64;
    const int d0 = (tile & 31) * 16;
    const int BUF = 32 * 68;                 // 2176 floats
    const int tn = tid & 15, tm = tid >> 4;

    // staging roles: 64 rows x 32 k, 4 threads/row, 8 k-floats each
    const int sj  = tid & 63;
    const int sk8 = (tid >> 6) * 8;          // 0,8,16,24
    const int wrow = ((sj >> 4) << 9) + d0 + (sj & 15);   // gate*512 + d

    ull acc[4][2];
#pragma unroll
    for (int im = 0; im < 4; im++) { acc[im][0] = 0ull; acc[im][1] = 0ull; }

    float4 a0, a1, w0, w1;
    {   // prefetch block 0 (A=x, W=Wih, kb=0)
        const float* ap = x + (size_t)(m0 + sj) * 512 + sk8;
        const float* wp = Wih + (size_t)wrow * 512 + sk8;
        a0 = *(const float4*)(ap);
        a1 = *(const float4*)(ap + 4);
        w0 = *(const float4*)(wp);
        w1 = *(const float4*)(wp + 4);
    }

    for (int i = 0; i < 32; i++) {
        float* as = sm + (i & 1) * (2 * BUF);
        float* ws = as + BUF;
        as[(sk8 + 0) * 68 + sj] = a0.x; as[(sk8 + 1) * 68 + sj] = a0.y;
        as[(sk8 + 2) * 68 + sj] = a0.z; as[(sk8 + 3) * 68 + sj] = a0.w;
        as[(sk8 + 4) * 68 + sj] = a1.x; as[(sk8 + 5) * 68 + sj] = a1.y;
        as[(sk8 + 6) * 68 + sj] = a1.z; as[(sk8 + 7) * 68 + sj] = a1.w;
        ws[(sk8 + 0) * 68 + sj] = w0.x; ws[(sk8 + 1) * 68 + sj] = w0.y;
        ws[(sk8 + 2) * 68 + sj] = w0.z; ws[(sk8 + 3) * 68 + sj] = w0.w;
        ws[(sk8 + 4) * 68 + sj] = w1.x; ws[(sk8 + 5) * 68 + sj] = w1.y;
        ws[(sk8 + 6) * 68 + sj] = w1.z; ws[(sk8 + 7) * 68 + sj] = w1.w;
        __syncthreads();
        if (i + 1 < 32) {
            int i2 = i + 1;
            const float* A = (i2 < 16) ? x : hin;
            const float* W = (i2 < 16) ? Wih : Whh;
            int kb = (i2 & 15) * 32;
            const float* ap = A + (size_t)(m0 + sj) * 512 + kb + sk8;
            const float* wp = W + (size_t)wrow * 512 + kb + sk8;
            a0 = *(const float4*)(ap);
            a1 = *(const float4*)(ap + 4);
            w0 = *(const float4*)(wp);
            w1 = *(const float4*)(wp + 4);
        }
#pragma unroll
        for (int k = 0; k < 32; k++) {
            float4 av = *(const float4*)(as + k * 68 + tm * 4);
            longlong2 wv = *(const longlong2*)(ws + k * 68 + tn * 4);
            ull wlo = (ull)wv.x, whi = (ull)wv.y;
            ull b0 = dup2(av.x), b1 = dup2(av.y), b2 = dup2(av.z), b3 = dup2(av.w);
            fma2(acc[0][0], b0, wlo); fma2(acc[0][1], b0, whi);
            fma2(acc[1][0], b1, wlo); fma2(acc[1][1], b1, whi);
            fma2(acc[2][0], b2, wlo); fma2(acc[2][1], b2, whi);
            fma2(acc[3][0], b3, wlo); fma2(acc[3][1], b3, whi);
        }
    }

    // epilogue: dump tile to smem G[64][66] (overlaps buf0 only; last compute
    // reads buf1 so no pre-sync needed), then fused pointwise LSTM update.
    float* G = sm;
#pragma unroll
    for (int im = 0; im < 4; im++) {
        int m = tm * 4 + im;
        float2 p0 = unpack2(acc[im][0]);
        float2 p1 = unpack2(acc[im][1]);
        *(float2*)(G + m * 66 + tn * 4)     = p0;
        *(float2*)(G + m * 66 + tn * 4 + 2) = p1;
    }
    __syncthreads();

    for (int e = tid; e < 1024; e += 256) {
        int m = e & 63, dp = e >> 6;
        int d = d0 + dp;
        float gi = G[m * 66 + dp]      + bih[d]        + bhh[d];
        float gf = G[m * 66 + 16 + dp] + bih[512 + d]  + bhh[512 + d];
        float gg = G[m * 66 + 32 + dp] + bih[1024 + d] + bhh[1024 + d];
        float go = G[m * 66 + 48 + dp] + bih[1536 + d] + bhh[1536 + d];
        int row = m0 + m;
        float si = 1.f / (1.f + expf(-gi));
        float sf = 1.f / (1.f + expf(-gf));
        float so = 1.f / (1.f + expf(-go));
        float cn = sf * cbuf[(size_t)row * 512 + d] + si * tanhf(gg);
        cbuf[(size_t)row * 512 + d] = cn;
        hout[(size_t)row * 512 + d] = so * tanhf(cn);
    }
}

// ---------------- attention for one batch row ----------------
__device__ __forceinline__ void attention_row(
    float* sm, int b, const float* __restrict__ h2,
    const float* __restrict__ enc, const float* __restrict__ encatt,
    const float* __restrict__ Wa1, const float* __restrict__ Wa2,
    const float* __restrict__ ba2, float* __restrict__ ctx)
{
    __syncthreads();
    float* sh_h  = sm;
    float* sh_hp = sm + 512;
    float* sh_s  = sm + 544;
    int tid = threadIdx.x;

    for (int k = tid; k < DD; k += 256) sh_h[k] = h2[(size_t)b * DD + k];
    __syncthreads();

    int warp = tid >> 5, lane = tid & 31;
    for (int j = warp; j < ATTH; j += 8) {
        const float* w = Wa1 + (size_t)j * (EENC + DD) + EENC;
        float s = 0.f;
        for (int k = lane; k < DD; k += 32) s += sh_h[k] * w[k];
#pragma unroll
        for (int o = 16; o; o >>= 1) s += __shfl_xor_sync(0xFFFFFFFFu, s, o);
        if (lane == 0) sh_hp[j] = s;
    }
    __syncthreads();

    if (tid < LL) {
        const float* ea = encatt + ((size_t)b * LL + tid) * ATTH;
        float s = 0.f;
#pragma unroll
        for (int j = 0; j < ATTH; j++) {
            float v = ea[j] + sh_hp[j];
            v = v > 0.f ? v : 0.f;
            s += v * Wa2[j];
        }
        sh_s[tid] = tanhf(s + ba2[0]);
    }
    __syncthreads();

    if (tid == 0) {
        float m = sh_s[0];
        for (int l = 1; l < LL; l++) m = fmaxf(m, sh_s[l]);
        float sum = 0.f;
        for (int l = 0; l < LL; l++) { float e = expf(sh_s[l] - m); sh_s[l] = e; sum += e; }
        float inv = 1.f / sum;
        for (int l = 0; l < LL; l++) sh_s[l] *= inv;
    }
    __syncthreads();

    const float* eb = enc + (size_t)b * LL * EENC;
    for (int k = tid; k < EENC; k += 256) {
        float s = 0.f;
#pragma unroll 8
        for (int l = 0; l < LL; l++) s += sh_s[l] * eb[(size_t)l * EENC + k];
        ctx[(size_t)b * EENC + k] = s;
    }
}

// ---------------- kernel params ----------------
struct Params {
    const int* act;
    const float* enc;
    const float* enc_h;
    const float* enc_c;
    const float* embW;
    const float* Wc;  const float* bc;
    const float* Wih[3]; const float* Whh[3];
    const float* bih[3]; const float* bhh[3];
    const float* Wa1; const float* ba1;
    const float* Wa2; const float* ba2;
    const float* Wl1; const float* bl1;
    const float* Wl2; const float* bl2;
    float* out;
};

// ---------------- persistent mega-kernel ----------------
__global__ void __launch_bounds__(256, 1) decoder_kernel(Params p)
{
    __shared__ __align__(16) float sm[8704];   // 34.8 KB
    const int nb  = gridDim.x;
    const int bid = blockIdx.x;
    const int tid = threadIdx.x;

    // ---- phase 0: setup ----
    for (int idx = bid * 256 + tid; idx < BB * DD; idx += nb * 256) {
        float h = p.enc_h[idx], c = p.enc_c[idx];
        g_h[0][0][idx] = h; g_h[1][0][idx] = h; g_h[2][0][idx] = h;
        g_c[0][idx] = c; g_c[1][idx] = c; g_c[2][idx] = c;
        g_ctx[idx] = 0.f;
    }
    for (int i4 = bid * 256 + tid; i4 < TT * BB * EMBW / 4; i4 += nb * 256) {
        int row = i4 >> 5;
        int kq  = i4 & 31;
        int t = row >> 8;
        int b = row & 255;
        float4 v = make_float4(0.f, 0.f, 0.f, 0.f);
        if (t > 0) {
            int a = p.act[b * TT + t - 1];
            v = *(const float4*)(p.embW + (size_t)a * EMBW + kq * 4);
        }
        *(float4*)(g_eseq + (size_t)row * EMBW + kq * 4) = v;
    }
    {
        int lane = tid & 31;
        int gw0 = (bid * 256 + tid) >> 5;
        for (int gw = gw0; gw < BB * LL; gw += nb * 8) {
            const float* er = p.enc + (size_t)gw * EENC;
            float r[16];
#pragma unroll
            for (int i = 0; i < 16; i++) r[i] = er[lane + 32 * i];
            for (int j = 0; j < ATTH; j++) {
                const float* w = p.Wa1 + (size_t)j * (EENC + DD);
                float s = 0.f;
#pragma unroll
                for (int i = 0; i < 16; i++) s += r[i] * w[lane + 32 * i];
#pragma unroll
                for (int o = 16; o; o >>= 1) s += __shfl_xor_sync(0xFFFFFFFFu, s, o);
                if (lane == 0) g_encatt[(size_t)gw * ATTH + j] = s + p.ba1[j];
            }
        }
    }
    gsync(nb);

    // ---- att for t=0: [e_0 | ctx0] @ Wc^T + bc ----
    for (int tile = bid; tile < 128; tile += nb)
        gemm32_tile(sm, tile, g_eseq, EMBW, g_ctx, EENC,
                    p.Wc, EMBW + EENC, p.bc, g_att, DD, DD, 0);
    gsync(nb);

    // ---- main loop ----
    for (int t = 0; t < TT; t++) {
        const int cur = t & 1, nxt = cur ^ 1;

        const float* xin = g_att;
        for (int cell = 0; cell < 3; cell++) {
            for (int tile = bid; tile < 128; tile += nb)
                lstm_tile(sm, tile, xin, g_h[cell][cur],
                          p.Wih[cell], p.Whh[cell], p.bih[cell], p.bhh[cell],
                          g_h[cell][nxt], g_c[cell]);
            gsync(nb);
            xin = g_h[cell][nxt];
        }

        for (int b = bid; b < BB; b += nb)
            attention_row(sm, b, g_h[2][nxt], p.enc, g_encatt,
                          p.Wa1, p.Wa2, p.ba2, g_ctx);
        gsync(nb);

        for (int tile = bid; tile < 128; tile += nb)
            gemm32_tile(sm, tile, g_h[2][nxt], DD, g_ctx, EENC,
                        p.Wl1, DD + EENC, p.bl1, g_act1, DD, DD, 1);
        gsync(nb);

        const int ntot = 40 + ((t + 1 < TT) ? 128 : 0);
        for (int u = bid; u < ntot; u += nb) {
            if (u < 40)
                gemm32_tile(sm, u, g_act1, DD, (const float*)0, 0,
                            p.Wl2, DD, p.bl2,
                            p.out + (size_t)t * AA, (size_t)TT * AA, AA, 0);
            else
                gemm32_tile(sm, u - 40,
                            g_eseq + (size_t)(t + 1) * BB * EMBW, EMBW, g_ctx, EENC,
                            p.Wc, EMBW + EENC, p.bc, g_att, DD, DD, 0);
        }
        gsync(nb);
    }
}

// ---------------- host ----------------
extern "C" void kernel_launch(void* const* d_in, const int* in_sizes, int n_in,
                              void* d_out, int out_size)
{
    Params p;
    p.act    = (const int*)  d_in[0];
    p.enc    = (const float*)d_in[1];
    p.enc_h  = (const float*)d_in[2];
    p.enc_c  = (const float*)d_in[3];
    p.embW   = (const float*)d_in[4];
    p.Wc     = (const float*)d_in[5];
    p.bc     = (const float*)d_in[6];
    p.Wih[0] = (const float*)d_in[7];  p.Whh[0] = (const float*)d_in[8];
    p.bih[0] = (const float*)d_in[9];  p.bhh[0] = (const float*)d_in[10];
    p.Wih[1] = (const float*)d_in[11]; p.Whh[1] = (const float*)d_in[12];
    p.bih[1] = (const float*)d_in[13]; p.bhh[1] = (const float*)d_in[14];
    p.Wih[2] = (const float*)d_in[15]; p.Whh[2] = (const float*)d_in[16];
    p.bih[2] = (const float*)d_in[17]; p.bhh[2] = (const float*)d_in[18];
    p.Wa1 = (const float*)d_in[19]; p.ba1 = (const float*)d_in[20];
    p.Wa2 = (const float*)d_in[21]; p.ba2 = (const float*)d_in[22];
    p.Wl1 = (const float*)d_in[23]; p.bl1 = (const float*)d_in[24];
    p.Wl2 = (const float*)d_in[25]; p.bl2 = (const float*)d_in[26];
    p.out = (float*)d_out;

    int dev = 0;
    cudaGetDevice(&dev);
    int nsm = 0;
    cudaDeviceGetAttribute(&nsm, cudaDevAttrMultiProcessorCount, dev);
    if (nsm <= 0) nsm = 148;

    decoder_kernel<<<nsm, 256>>>(p);
}

// round 5
// speedup vs baseline: 1.2706x; 1.1450x over previous
#include <cuda_runtime.h>
#include <math.h>

#define BB   256
#define TT   128
#define LL   64
#define EENC 512
#define DD   512
#define EMBW 128
#define AA   129
#define ATTH 20

#define NT        512                // threads per block (two 256-thread halves)
#define BUF32     (32 * 68)          // LSTM staging buffer (floats)
#define HALF_FL   (4 * BUF32)        // per-half smem region: 8704 floats
#define SMEM_FL   (2 * HALF_FL)      // 17408 floats = 69632 B
#define BUF16     (16 * 36)          // 32x32 GEMM staging buffer

typedef unsigned long long ull;

// ---------------- device scratch (static, no allocs) ----------------
__device__ __align__(16) float g_eseq[TT * BB * EMBW];
__device__ __align__(16) float g_encatt[BB * LL * ATTH];
__device__ __align__(16) float g_att[BB * DD];
__device__ __align__(16) float g_h[3][2][BB * DD];
__device__ __align__(16) float g_c[3][BB * DD];
__device__ __align__(16) float g_ctx[BB * EENC];
__device__ __align__(16) float g_act1[BB * DD];

__device__ unsigned int g_bar_count = 0;
__device__ unsigned int g_bar_gen   = 0;

// ---------------- packed f32x2 helpers ----------------
__device__ __forceinline__ ull dup2(float x) {
    ull r;
    asm("mov.b64 %0, {%1, %1};" : "=l"(r) : "f"(x));
    return r;
}
__device__ __forceinline__ void fma2(ull& d, ull a, ull b) {
    asm("fma.rn.f32x2 %0, %1, %2, %0;" : "+l"(d) : "l"(a), "l"(b));
}
__device__ __forceinline__ float2 unpack2(ull v) {
    float2 r;
    asm("mov.b64 {%0, %1}, %2;" : "=f"(r.x), "=f"(r.y) : "l"(v));
    return r;
}

// ---------------- launch-reentrant grid barrier ----------------
__device__ __forceinline__ void gsync(int nb) {
    __syncthreads();
    if (threadIdx.x == 0) {
        __threadfence();
        unsigned int gen = *(volatile unsigned int*)&g_bar_gen;
        if (atomicAdd(&g_bar_count, 1u) == (unsigned int)(nb - 1)) {
            g_bar_count = 0;
            __threadfence();
            atomicAdd(&g_bar_gen, 1u);
        } else {
            while (*(volatile unsigned int*)&g_bar_gen == gen) { }
        }
        __threadfence();
    }
    __syncthreads();
}

// ---------------- 32x32 cat-GEMM tile, split-K across halves ----------------
// C = [A1|A2] @ W^T + bias.  half0 does K[0, K/2), half1 does K[K/2, K).
// half1 dumps its partial to smem; half0 combines + stores.
__device__ __forceinline__ void gemm32_tile512(
    float* sm, int tile,
    const float* __restrict__ A1, int K1,
    const float* __restrict__ A2, int K2,
    const float* __restrict__ W, int ldw,
    const float* __restrict__ bias,
    float* __restrict__ C, size_t ldc, int N, int relu)
{
    __syncthreads();
    const int tid  = threadIdx.x;
    const int half = tid >> 8;
    const int htid = tid & 255;
    float* hb = sm + half * HALF_FL;

    const int ntN = (N + 31) >> 5;
    const int m0 = (tile / ntN) * 32;
    const int n0 = (tile % ntN) * 32;
    const int tn = htid & 15, tm = htid >> 4;
    ull acc0 = 0ull, acc1 = 0ull;

    const int K = K1 + K2;
    const int kbase = half * (K >> 1);
    const int nk = (K >> 1) >> 4;

    const bool isA = htid < 128;
    const int srow = (htid & 127) >> 2;
    const int skq  = (htid & 3) * 4;

    float4 v;
    {
        int k0 = kbase;
        if (isA) {
            const float* A; int lda, kb;
            if (k0 < K1) { A = A1; lda = K1; kb = k0; }
            else         { A = A2; lda = K2; kb = k0 - K1; }
            v = *(const float4*)(A + (size_t)(m0 + srow) * lda + kb + skq);
        } else {
            v = make_float4(0.f, 0.f, 0.f, 0.f);
            if (n0 + srow < N)
                v = *(const float4*)(W + (size_t)(n0 + srow) * ldw + k0 + skq);
        }
    }

    for (int i = 0; i < nk; i++) {
        float* as = hb + (i & 1) * (2 * BUF16);
        float* ws = as + BUF16;
        float* dst = isA ? as : ws;
        dst[(skq + 0) * 36 + srow] = v.x;
        dst[(skq + 1) * 36 + srow] = v.y;
        dst[(skq + 2) * 36 + srow] = v.z;
        dst[(skq + 3) * 36 + srow] = v.w;
        __syncthreads();
        if (i + 1 < nk) {
            int k0 = kbase + ((i + 1) << 4);
            if (isA) {
                const float* A; int lda, kb;
                if (k0 < K1) { A = A1; lda = K1; kb = k0; }
                else         { A = A2; lda = K2; kb = k0 - K1; }
                v = *(const float4*)(A + (size_t)(m0 + srow) * lda + kb + skq);
            } else {
                v = make_float4(0.f, 0.f, 0.f, 0.f);
                if (n0 + srow < N)
                    v = *(const float4*)(W + (size_t)(n0 + srow) * ldw + k0 + skq);
            }
        }
#pragma unroll
        for (int k = 0; k < 16; k++) {
            float2 a2 = *(const float2*)(as + k * 36 + tm * 2);
            ull wv = *(const ull*)(ws + k * 36 + tn * 2);
            fma2(acc0, dup2(a2.x), wv);
            fma2(acc1, dup2(a2.y), wv);
        }
    }

    // combine: half1 -> smem partial, half0 adds & stores
    __syncthreads();
    float* P = sm + HALF_FL;               // half1's region (staging consumed)
    if (half == 1) {
        *(float2*)(P + (tm * 2 + 0) * 34 + tn * 2) = unpack2(acc0);
        *(float2*)(P + (tm * 2 + 1) * 34 + tn * 2) = unpack2(acc1);
    }
    __syncthreads();
    if (half == 0) {
        float2 p0 = unpack2(acc0);
        float2 p1 = unpack2(acc1);
        float2 q0 = *(const float2*)(P + (tm * 2 + 0) * 34 + tn * 2);
        float2 q1 = *(const float2*)(P + (tm * 2 + 1) * 34 + tn * 2);
        int n_a = n0 + tn * 2, n_b = n_a + 1;
        int m_a = m0 + tm * 2, m_b = m_a + 1;
        if (n_a < N) {
            float v0 = p0.x + q0.x + bias[n_a];
            float v1 = p1.x + q1.x + bias[n_a];
            if (relu) { v0 = fmaxf(v0, 0.f); v1 = fmaxf(v1, 0.f); }
            C[(size_t)m_a * ldc + n_a] = v0;
            C[(size_t)m_b * ldc + n_a] = v1;
        }
        if (n_b < N) {
            float v0 = p0.y + q0.y + bias[n_b];
            float v1 = p1.y + q1.y + bias[n_b];
            if (relu) { v0 = fmaxf(v0, 0.f); v1 = fmaxf(v1, 0.f); }
            C[(size_t)m_a * ldc + n_b] = v0;
            C[(size_t)m_b * ldc + n_b] = v1;
        }
    }
}

// ---------------- LSTM 64x64 tile: half0 = x@Wih, half1 = h@Whh ----------------
// N-tile covers d in [d0, d0+16) for ALL 4 gates via W-row remap; fused pointwise.
__device__ __forceinline__ void lstm_tile512(
    float* sm, int tile,
    const float* __restrict__ x, const float* __restrict__ hin,
    const float* __restrict__ Wih, const float* __restrict__ Whh,
    const float* __restrict__ bih, const float* __restrict__ bhh,
    float* __restrict__ hout, float* __restrict__ cbuf)
{
    __syncthreads();
    const int tid  = threadIdx.x;
    const int half = tid >> 8;
    const int htid = tid & 255;
    float* hb = sm + half * HALF_FL;

    const int m0 = (tile >> 5) * 64;
    const int d0 = (tile & 31) * 16;
    const int tn = htid & 15, tm = htid >> 4;

    const float* __restrict__ A = half ? hin : x;
    const float* __restrict__ W = half ? Whh : Wih;

    // staging roles: 64 rows x 32 k, 4 threads/row, 8 k-floats each
    const int sj  = htid & 63;
    const int sk8 = (htid >> 6) * 8;
    const int wrow = ((sj >> 4) << 9) + d0 + (sj & 15);   // gate*512 + d

    ull acc[4][2];
#pragma unroll
    for (int im = 0; im < 4; im++) { acc[im][0] = 0ull; acc[im][1] = 0ull; }

    float4 a0, a1, w0, w1;
    {
        const float* ap = A + (size_t)(m0 + sj) * 512 + sk8;
        const float* wp = W + (size_t)wrow * 512 + sk8;
        a0 = *(const float4*)(ap);
        a1 = *(const float4*)(ap + 4);
        w0 = *(const float4*)(wp);
        w1 = *(const float4*)(wp + 4);
    }

    for (int i = 0; i < 16; i++) {
        float* as = hb + (i & 1) * (2 * BUF32);
        float* ws = as + BUF32;
        as[(sk8 + 0) * 68 + sj] = a0.x; as[(sk8 + 1) * 68 + sj] = a0.y;
        as[(sk8 + 2) * 68 + sj] = a0.z; as[(sk8 + 3) * 68 + sj] = a0.w;
        as[(sk8 + 4) * 68 + sj] = a1.x; as[(sk8 + 5) * 68 + sj] = a1.y;
        as[(sk8 + 6) * 68 + sj] = a1.z; as[(sk8 + 7) * 68 + sj] = a1.w;
        ws[(sk8 + 0) * 68 + sj] = w0.x; ws[(sk8 + 1) * 68 + sj] = w0.y;
        ws[(sk8 + 2) * 68 + sj] = w0.z; ws[(sk8 + 3) * 68 + sj] = w0.w;
        ws[(sk8 + 4) * 68 + sj] = w1.x; ws[(sk8 + 5) * 68 + sj] = w1.y;
        ws[(sk8 + 6) * 68 + sj] = w1.z; ws[(sk8 + 7) * 68 + sj] = w1.w;
        __syncthreads();
        if (i + 1 < 16) {
            int kb = (i + 1) * 32;
            const float* ap = A + (size_t)(m0 + sj) * 512 + kb + sk8;
            const float* wp = W + (size_t)wrow * 512 + kb + sk8;
            a0 = *(const float4*)(ap);
            a1 = *(const float4*)(ap + 4);
            w0 = *(const float4*)(wp);
            w1 = *(const float4*)(wp + 4);
        }
#pragma unroll
        for (int k = 0; k < 32; k++) {
            float4 av = *(const float4*)(as + k * 68 + tm * 4);
            longlong2 wv = *(const longlong2*)(ws + k * 68 + tn * 4);
            ull wlo = (ull)wv.x, whi = (ull)wv.y;
            ull b0 = dup2(av.x), b1 = dup2(av.y), b2 = dup2(av.z), b3 = dup2(av.w);
            fma2(acc[0][0], b0, wlo); fma2(acc[0][1], b0, whi);
            fma2(acc[1][0], b1, wlo); fma2(acc[1][1], b1, whi);
            fma2(acc[2][0], b2, wlo); fma2(acc[2][1], b2, whi);
            fma2(acc[3][0], b3, wlo); fma2(acc[3][1], b3, whi);
        }
    }

    // epilogue: both halves dump their 64x64 partial to their own region,
    // then 512 threads do the fused pointwise on the summed gates.
    __syncthreads();
    float* G = hb;                        // staging consumed
#pragma unroll
    for (int im = 0; im < 4; im++) {
        int m = tm * 4 + im;
        *(float2*)(G + m * 66 + tn * 4)     = unpack2(acc[im][0]);
        *(float2*)(G + m * 66 + tn * 4 + 2) = unpack2(acc[im][1]);
    }
    __syncthreads();

    float* G0 = sm;
    float* G1 = sm + HALF_FL;
    for (int e = tid; e < 1024; e += NT) {
        int m = e & 63, dp = e >> 6;
        int d = d0 + dp;
        float gi = G0[m * 66 + dp]      + G1[m * 66 + dp]      + bih[d]        + bhh[d];
        float gf = G0[m * 66 + 16 + dp] + G1[m * 66 + 16 + dp] + bih[512 + d]  + bhh[512 + d];
        float gg = G0[m * 66 + 32 + dp] + G1[m * 66 + 32 + dp] + bih[1024 + d] + bhh[1024 + d];
        float go = G0[m * 66 + 48 + dp] + G1[m * 66 + 48 + dp] + bih[1536 + d] + bhh[1536 + d];
        int row = m0 + m;
        float si = 1.f / (1.f + expf(-gi));
        float sf = 1.f / (1.f + expf(-gf));
        float so = 1.f / (1.f + expf(-go));
        float cn = sf * cbuf[(size_t)row * 512 + d] + si * tanhf(gg);
        cbuf[(size_t)row * 512 + d] = cn;
        hout[(size_t)row * 512 + d] = so * tanhf(cn);
    }
}

// ---------------- attention for one batch row (512 threads) ----------------
__device__ __forceinline__ void attention_row(
    float* sm, int b, const float* __restrict__ h2,
    const float* __restrict__ enc, const float* __restrict__ encatt,
    const float* __restrict__ Wa1, const float* __restrict__ Wa2,
    const float* __restrict__ ba2, float* __restrict__ ctx)
{
    __syncthreads();
    float* sh_h  = sm;
    float* sh_hp = sm + 512;
    float* sh_s  = sm + 544;
    int tid = threadIdx.x;

    for (int k = tid; k < DD; k += NT) sh_h[k] = h2[(size_t)b * DD + k];
    __syncthreads();

    int warp = tid >> 5, lane = tid & 31;
    for (int j = warp; j < ATTH; j += 16) {
        const float* w = Wa1 + (size_t)j * (EENC + DD) + EENC;
        float s = 0.f;
        for (int k = lane; k < DD; k += 32) s += sh_h[k] * w[k];
#pragma unroll
        for (int o = 16; o; o >>= 1) s += __shfl_xor_sync(0xFFFFFFFFu, s, o);
        if (lane == 0) sh_hp[j] = s;
    }
    __syncthreads();

    if (tid < LL) {
        const float* ea = encatt + ((size_t)b * LL + tid) * ATTH;
        float s = 0.f;
#pragma unroll
        for (int j = 0; j < ATTH; j++) {
            float v = ea[j] + sh_hp[j];
            v = v > 0.f ? v : 0.f;
            s += v * Wa2[j];
        }
        sh_s[tid] = tanhf(s + ba2[0]);
    }
    __syncthreads();

    if (tid == 0) {
        float m = sh_s[0];
        for (int l = 1; l < LL; l++) m = fmaxf(m, sh_s[l]);
        float sum = 0.f;
        for (int l = 0; l < LL; l++) { float e = expf(sh_s[l] - m); sh_s[l] = e; sum += e; }
        float inv = 1.f / sum;
        for (int l = 0; l < LL; l++) sh_s[l] *= inv;
    }
    __syncthreads();

    const float* eb = enc + (size_t)b * LL * EENC;
    for (int k = tid; k < EENC; k += NT) {
        float s = 0.f;
#pragma unroll 8
        for (int l = 0; l < LL; l++) s += sh_s[l] * eb[(size_t)l * EENC + k];
        ctx[(size_t)b * EENC + k] = s;
    }
}

// ---------------- kernel params ----------------
struct Params {
    const int* act;
    const float* enc;
    const float* enc_h;
    const float* enc_c;
    const float* embW;
    const float* Wc;  const float* bc;
    const float* Wih[3]; const float* Whh[3];
    const float* bih[3]; const float* bhh[3];
    const float* Wa1; const float* ba1;
    const float* Wa2; const float* ba2;
    const float* Wl1; const float* bl1;
    const float* Wl2; const float* bl2;
    float* out;
};

// ---------------- persistent mega-kernel ----------------
__global__ void __launch_bounds__(NT, 1) decoder_kernel(Params p)
{
    extern __shared__ __align__(16) float sm[];
    const int nb  = gridDim.x;
    const int bid = blockIdx.x;
    const int tid = threadIdx.x;

    // ---- phase 0: setup ----
    for (int idx = bid * NT + tid; idx < BB * DD; idx += nb * NT) {
        float h = p.enc_h[idx], c = p.enc_c[idx];
        g_h[0][0][idx] = h; g_h[1][0][idx] = h; g_h[2][0][idx] = h;
        g_c[0][idx] = c; g_c[1][idx] = c; g_c[2][idx] = c;
        g_ctx[idx] = 0.f;
    }
    for (int i4 = bid * NT + tid; i4 < TT * BB * EMBW / 4; i4 += nb * NT) {
        int row = i4 >> 5;
        int kq  = i4 & 31;
        int t = row >> 8;
        int b = row & 255;
        float4 v = make_float4(0.f, 0.f, 0.f, 0.f);
        if (t > 0) {
            int a = p.act[b * TT + t - 1];
            v = *(const float4*)(p.embW + (size_t)a * EMBW + kq * 4);
        }
        *(float4*)(g_eseq + (size_t)row * EMBW + kq * 4) = v;
    }
    {
        int lane = tid & 31;
        int gw0 = (bid * NT + tid) >> 5;
        for (int gw = gw0; gw < BB * LL; gw += nb * (NT / 32)) {
            const float* er = p.enc + (size_t)gw * EENC;
            float r[16];
#pragma unroll
            for (int i = 0; i < 16; i++) r[i] = er[lane + 32 * i];
            for (int j = 0; j < ATTH; j++) {
                const float* w = p.Wa1 + (size_t)j * (EENC + DD);
                float s = 0.f;
#pragma unroll
                for (int i = 0; i < 16; i++) s += r[i] * w[lane + 32 * i];
#pragma unroll
                for (int o = 16; o; o >>= 1) s += __shfl_xor_sync(0xFFFFFFFFu, s, o);
                if (lane == 0) g_encatt[(size_t)gw * ATTH + j] = s + p.ba1[j];
            }
        }
    }
    gsync(nb);

    // ---- att for t=0 ----
    for (int tile = bid; tile < 128; tile += nb)
        gemm32_tile512(sm, tile, g_eseq, EMBW, g_ctx, EENC,
                       p.Wc, EMBW + EENC, p.bc, g_att, DD, DD, 0);
    gsync(nb);

    // ---- main loop ----
    for (int t = 0; t < TT; t++) {
        const int cur = t & 1, nxt = cur ^ 1;

        const float* xin = g_att;
        for (int cell = 0; cell < 3; cell++) {
            for (int tile = bid; tile < 128; tile += nb)
                lstm_tile512(sm, tile, xin, g_h[cell][cur],
                             p.Wih[cell], p.Whh[cell], p.bih[cell], p.bhh[cell],
                             g_h[cell][nxt], g_c[cell]);
            gsync(nb);
            xin = g_h[cell][nxt];
        }

        for (int b = bid; b < BB; b += nb)
            attention_row(sm, b, g_h[2][nxt], p.enc, g_encatt,
                          p.Wa1, p.Wa2, p.ba2, g_ctx);
        gsync(nb);

        for (int tile = bid; tile < 128; tile += nb)
            gemm32_tile512(sm, tile, g_h[2][nxt], DD, g_ctx, EENC,
                           p.Wl1, DD + EENC, p.bl1, g_act1, DD, DD, 1);
        gsync(nb);

        const int ntot = 40 + ((t + 1 < TT) ? 128 : 0);
        for (int u = bid; u < ntot; u += nb) {
            if (u < 40)
                gemm32_tile512(sm, u, g_act1, DD, (const float*)0, 0,
                               p.Wl2, DD, p.bl2,
                               p.out + (size_t)t * AA, (size_t)TT * AA, AA, 0);
            else
                gemm32_tile512(sm, u - 40,
                               g_eseq + (size_t)(t + 1) * BB * EMBW, EMBW, g_ctx, EENC,
                               p.Wc, EMBW + EENC, p.bc, g_att, DD, DD, 0);
        }
        gsync(nb);
    }
}

// ---------------- host ----------------
extern "C" void kernel_launch(void* const* d_in, const int* in_sizes, int n_in,
                              void* d_out, int out_size)
{
    Params p;
    p.act    = (const int*)  d_in[0];
    p.enc    = (const float*)d_in[1];
    p.enc_h  = (const float*)d_in[2];
    p.enc_c  = (const float*)d_in[3];
    p.embW   = (const float*)d_in[4];
    p.Wc     = (const float*)d_in[5];
    p.bc     = (const float*)d_in[6];
    p.Wih[0] = (const float*)d_in[7];  p.Whh[0] = (const float*)d_in[8];
    p.bih[0] = (const float*)d_in[9];  p.bhh[0] = (const float*)d_in[10];
    p.Wih[1] = (const float*)d_in[11]; p.Whh[1] = (const float*)d_in[12];
    p.bih[1] = (const float*)d_in[13]; p.bhh[1] = (const float*)d_in[14];
    p.Wih[2] = (const float*)d_in[15]; p.Whh[2] = (const float*)d_in[16];
    p.bih[2] = (const float*)d_in[17]; p.bhh[2] = (const float*)d_in[18];
    p.Wa1 = (const float*)d_in[19]; p.ba1 = (const float*)d_in[20];
    p.Wa2 = (const float*)d_in[21]; p.ba2 = (const float*)d_in[22];
    p.Wl1 = (const float*)d_in[23]; p.bl1 = (const float*)d_in[24];
    p.Wl2 = (const float*)d_in[25]; p.bl2 = (const float*)d_in[26];
    p.out = (float*)d_out;

    int dev = 0;
    cudaGetDevice(&dev);
    int nsm = 0;
    cudaDeviceGetAttribute(&nsm, cudaDevAttrMultiProcessorCount, dev);
    if (nsm <= 0) nsm = 148;

    const int smem_bytes = SMEM_FL * sizeof(float);   // 69632
    cudaFuncSetAttribute(decoder_kernel,
                         cudaFuncAttributeMaxDynamicSharedMemorySize, smem_bytes);
    decoder_kernel<<<nsm, NT, smem_bytes>>>(p);
}

// round 6
// speedup vs baseline: 2.0661x; 1.6261x over previous
#include <cuda_runtime.h>
#include <cuda_bf16.h>
#include <math.h>

#define BB   256
#define TT   128
#define LL   64
#define EENC 512
#define DD   512
#define EMBW 128
#define AA   129
#define ATTH 20

#define NT   512

#define PIT    40                  // smem row pitch in bf16 elems (80B, ldsm conflict-free)
#define MATSZ  (64 * PIT)          // one 64x32 staged matrix (2560 elems)
#define BUFE   (4 * MATSZ)         // Ahi, Alo, Whi, Wlo per stage (10240 elems)
#define SMEM_BYTES (2 * BUFE * 2)  // double-buffered, bytes (40960)

typedef unsigned int u32;
typedef __nv_bfloat16 bf;

// ---------------- device scratch (static, no allocs) ----------------
__device__ __align__(16) bf    g_eseq_h[TT * BB * EMBW];
__device__ __align__(16) bf    g_eseq_l[TT * BB * EMBW];
__device__ __align__(16) float g_encatt[BB * LL * ATTH];
__device__ __align__(16) bf    g_att_h[BB * DD],  g_att_l[BB * DD];
__device__ __align__(16) float g_hf[3][2][BB * DD];
__device__ __align__(16) bf    g_hh[3][2][BB * DD], g_hl[3][2][BB * DD];
__device__ __align__(16) float g_c[3][BB * DD];
__device__ __align__(16) bf    g_ctx_h[BB * EENC], g_ctx_l[BB * EENC];
__device__ __align__(16) bf    g_act1_h[BB * DD],  g_act1_l[BB * DD];

__device__ __align__(16) bf g_Wc_h[DD * (EMBW + EENC)],  g_Wc_l[DD * (EMBW + EENC)];
__device__ __align__(16) bf g_Wih_h[3][4 * DD * DD], g_Wih_l[3][4 * DD * DD];
__device__ __align__(16) bf g_Whh_h[3][4 * DD * DD], g_Whh_l[3][4 * DD * DD];
__device__ __align__(16) bf g_Wl1_h[DD * (DD + EENC)], g_Wl1_l[DD * (DD + EENC)];
__device__ __align__(16) bf g_Wl2_h[AA * DD], g_Wl2_l[AA * DD];

__device__ unsigned int g_bar_count = 0;
__device__ unsigned int g_bar_gen   = 0;

// ---------------- helpers ----------------
__device__ __forceinline__ void split_bf(float x, bf& h, bf& l) {
    h = __float2bfloat16(x);
    l = __float2bfloat16(x - __bfloat162float(h));
}

__device__ __forceinline__ u32 sptr(const void* p) {
    return (u32)__cvta_generic_to_shared(p);
}

__device__ __forceinline__ void ldsm4(u32* r, u32 a) {
    asm volatile("ldmatrix.sync.aligned.m8n8.x4.shared.b16 {%0,%1,%2,%3}, [%4];"
                 : "=r"(r[0]), "=r"(r[1]), "=r"(r[2]), "=r"(r[3]) : "r"(a));
}

__device__ __forceinline__ void mma16816(float* d, const u32* a, const u32* b) {
    asm volatile(
        "mma.sync.aligned.m16n8k16.row.col.f32.bf16.bf16.f32 "
        "{%0,%1,%2,%3},{%4,%5,%6,%7},{%8,%9},{%0,%1,%2,%3};"
        : "+f"(d[0]), "+f"(d[1]), "+f"(d[2]), "+f"(d[3])
        : "r"(a[0]), "r"(a[1]), "r"(a[2]), "r"(a[3]), "r"(b[0]), "r"(b[1]));
}

// ---------------- launch-reentrant grid barrier ----------------
__device__ __forceinline__ void gsync(int nb) {
    __syncthreads();
    if (threadIdx.x == 0) {
        __threadfence();
        unsigned int gen = *(volatile unsigned int*)&g_bar_gen;
        if (atomicAdd(&g_bar_count, 1u) == (unsigned int)(nb - 1)) {
            g_bar_count = 0;
            __threadfence();
            atomicAdd(&g_bar_gen, 1u);
        } else {
            while (*(volatile unsigned int*)&g_bar_gen == gen) { }
        }
        __threadfence();
    }
    __syncthreads();
}

// ---------------- generic 64x64 mma tile: C = [A1|A2] @ W^T + bias ----------------
// All operands split-bf16 (hi/lo). 3-product accumulation: AhBh + AhBl + AlBh.
__device__ __forceinline__ void mm_tile(
    bf* stg, int tile,
    const bf* __restrict__ A1h, const bf* __restrict__ A1l, int K1,
    const bf* __restrict__ A2h, const bf* __restrict__ A2l, int K2,
    const bf* __restrict__ Wh,  const bf* __restrict__ Wl, int ldw, int N,
    const float* __restrict__ bias, int relu,
    float* __restrict__ Cf, size_t ldc,
    bf* __restrict__ Ch, bf* __restrict__ Cl, int ldcb)
{
    __syncthreads();
    const int tid = threadIdx.x;
    const int lane = tid & 31, warp = tid >> 5;
    const int wm = warp >> 2, wn = warp & 3;
    const int ntN = (N + 63) >> 6;
    const int m0 = (tile / ntN) * 64, n0 = (tile % ntN) * 64;
    const int S = (K1 + K2) >> 5;

    const int smat = tid >> 8;             // 0=hi, 1=lo
    const int srow = (tid >> 2) & 63;
    const int sseg = (tid & 3) * 8;
    const int wrow = n0 + srow;
    const bool wok = (wrow < N);

    float acc[2][4] = {};
    uint4 va, vw;
    {   // prefetch stage 0
        const bf* Ap; int lda;
        if (K1 > 0) { Ap = smat ? A1l : A1h; lda = K1; }
        else        { Ap = smat ? A2l : A2h; lda = K2; }
        va = *(const uint4*)(Ap + (size_t)(m0 + srow) * lda + sseg);
        vw = make_uint4(0u, 0u, 0u, 0u);
        if (wok) {
            const bf* Wp = smat ? Wl : Wh;
            vw = *(const uint4*)(Wp + (size_t)wrow * ldw + sseg);
        }
    }

    for (int s = 0; s < S; s++) {
        bf* buf = stg + (s & 1) * BUFE;
        *(uint4*)(buf + smat * MATSZ + srow * PIT + sseg) = va;
        *(uint4*)(buf + (2 + smat) * MATSZ + srow * PIT + sseg) = vw;
        __syncthreads();
        if (s + 1 < S) {
            int kb = (s + 1) << 5;
            const bf* Ap; int lda, ka;
            if (kb < K1) { Ap = smat ? A1l : A1h; lda = K1; ka = kb; }
            else         { Ap = smat ? A2l : A2h; lda = K2; ka = kb - K1; }
            va = *(const uint4*)(Ap + (size_t)(m0 + srow) * lda + ka + sseg);
            vw = make_uint4(0u, 0u, 0u, 0u);
            if (wok) {
                const bf* Wp = smat ? Wl : Wh;
                vw = *(const uint4*)(Wp + (size_t)wrow * ldw + kb + sseg);
            }
        }
#pragma unroll
        for (int q = 0; q < 2; q++) {
            u32 ah[4], al[4], bh[4], bl[4];
            u32 abase = sptr(buf + (wm * 16 + (lane & 15)) * PIT
                                 + q * 16 + ((lane >> 4) & 1) * 8);
            ldsm4(ah, abase);
            ldsm4(al, abase + MATSZ * 2);
            u32 bbase = sptr(buf + 2 * MATSZ
                                 + (wn * 16 + (lane & 7) + ((lane >> 4) & 1) * 8) * PIT
                                 + q * 16 + ((lane >> 3) & 1) * 8);
            ldsm4(bh, bbase);
            ldsm4(bl, bbase + MATSZ * 2);
            mma16816(acc[0], ah, bh + 0);
            mma16816(acc[1], ah, bh + 2);
            mma16816(acc[0], ah, bl + 0);
            mma16816(acc[1], ah, bl + 2);
            mma16816(acc[0], al, bh + 0);
            mma16816(acc[1], al, bh + 2);
        }
    }

    // epilogue (register-only + gmem)
#pragma unroll
    for (int bb = 0; bb < 2; bb++) {
        int nc = n0 + wn * 16 + bb * 8 + (lane & 3) * 2;
        int r0 = m0 + wm * 16 + (lane >> 2);
#pragma unroll
        for (int hf = 0; hf < 2; hf++) {
            int r = r0 + hf * 8;
#pragma unroll
            for (int j = 0; j < 2; j++) {
                int n = nc + j;
                if (n < N) {
                    float v = acc[bb][hf * 2 + j] + bias[n];
                    if (relu) v = fmaxf(v, 0.f);
                    if (Cf) Cf[(size_t)r * ldc + n] = v;
                    if (Ch) {
                        bf vh, vl; split_bf(v, vh, vl);
                        Ch[(size_t)r * ldcb + n] = vh;
                        Cl[(size_t)r * ldcb + n] = vl;
                    }
                }
            }
        }
    }
}

// ---------------- LSTM 64x64 mma tile with gate remap + fused pointwise ----------
__device__ __forceinline__ void lstm_mma(
    bf* stg, int tile,
    const bf* __restrict__ xh, const bf* __restrict__ xl,
    const bf* __restrict__ hhx, const bf* __restrict__ hlx,
    const bf* __restrict__ Wihh, const bf* __restrict__ Wihl,
    const bf* __restrict__ Whhh, const bf* __restrict__ Whhl,
    const float* __restrict__ bih, const float* __restrict__ bhh,
    float* __restrict__ houtf, bf* __restrict__ houth, bf* __restrict__ houtl,
    float* __restrict__ cbuf)
{
    __syncthreads();
    const int tid = threadIdx.x;
    const int lane = tid & 31, warp = tid >> 5;
    const int wm = warp >> 2, wn = warp & 3;
    const int m0 = (tile >> 5) * 64;
    const int d0 = (tile & 31) * 16;

    const int smat = tid >> 8;
    const int srow = (tid >> 2) & 63;
    const int sseg = (tid & 3) * 8;
    const int wrow = ((srow >> 4) << 9) + d0 + (srow & 15);   // gate*512 + d

    float acc[2][4] = {};
    uint4 va, vw;
    {
        const bf* Ap = smat ? xl : xh;
        const bf* Wp = smat ? Wihl : Wihh;
        va = *(const uint4*)(Ap + (size_t)(m0 + srow) * 512 + sseg);
        vw = *(const uint4*)(Wp + (size_t)wrow * 512 + sseg);
    }

    for (int s = 0; s < 32; s++) {
        bf* buf = stg + (s & 1) * BUFE;
        *(uint4*)(buf + smat * MATSZ + srow * PIT + sseg) = va;
        *(uint4*)(buf + (2 + smat) * MATSZ + srow * PIT + sseg) = vw;
        __syncthreads();
        if (s + 1 < 32) {
            int s2 = s + 1;
            const bf* Ap = (s2 < 16) ? (smat ? xl : xh) : (smat ? hlx : hhx);
            const bf* Wp = (s2 < 16) ? (smat ? Wihl : Wihh) : (smat ? Whhl : Whhh);
            int kb = (s2 & 15) * 32;
            va = *(const uint4*)(Ap + (size_t)(m0 + srow) * 512 + kb + sseg);
            vw = *(const uint4*)(Wp + (size_t)wrow * 512 + kb + sseg);
        }
#pragma unroll
        for (int q = 0; q < 2; q++) {
            u32 ah[4], al[4], bh[4], bl[4];
            u32 abase = sptr(buf + (wm * 16 + (lane & 15)) * PIT
                                 + q * 16 + ((lane >> 4) & 1) * 8);
            ldsm4(ah, abase);
            ldsm4(al, abase + MATSZ * 2);
            u32 bbase = sptr(buf + 2 * MATSZ
                                 + (wn * 16 + (lane & 7) + ((lane >> 4) & 1) * 8) * PIT
                                 + q * 16 + ((lane >> 3) & 1) * 8);
            ldsm4(bh, bbase);
            ldsm4(bl, bbase + MATSZ * 2);
            mma16816(acc[0], ah, bh + 0);
            mma16816(acc[1], ah, bh + 2);
            mma16816(acc[0], ah, bl + 0);
            mma16816(acc[1], ah, bl + 2);
            mma16816(acc[0], al, bh + 0);
            mma16816(acc[1], al, bh + 2);
        }
    }

    // dump C frags to smem G[64][68] in buf0 region (last stage read buf1)
    float* G = (float*)stg;
#pragma unroll
    for (int bb = 0; bb < 2; bb++) {
        int c = wn * 16 + bb * 8 + (lane & 3) * 2;
        int r0 = wm * 16 + (lane >> 2);
        *(float2*)(G + r0 * 68 + c)       = make_float2(acc[bb][0], acc[bb][1]);
        *(float2*)(G + (r0 + 8) * 68 + c) = make_float2(acc[bb][2], acc[bb][3]);
    }
    __syncthreads();

    for (int e = tid; e < 1024; e += NT) {
        int m = e & 63, dp = e >> 6;
        int d = d0 + dp;
        const float* Gm = G + m * 68;
        float gi = Gm[dp]      + bih[d]        + bhh[d];
        float gf = Gm[16 + dp] + bih[512 + d]  + bhh[512 + d];
        float gg = Gm[32 + dp] + bih[1024 + d] + bhh[1024 + d];
        float go = Gm[48 + dp] + bih[1536 + d] + bhh[1536 + d];
        size_t idx = (size_t)(m0 + m) * 512 + d;
        float si = 1.f / (1.f + expf(-gi));
        float sf = 1.f / (1.f + expf(-gf));
        float so = 1.f / (1.f + expf(-go));
        float cn = sf * cbuf[idx] + si * tanhf(gg);
        cbuf[idx] = cn;
        float hn = so * tanhf(cn);
        houtf[idx] = hn;
        bf vh, vl; split_bf(hn, vh, vl);
        houth[idx] = vh;
        houtl[idx] = vl;
    }
}

// ---------------- attention for one batch row (512 threads) ----------------
__device__ __forceinline__ void attention_row(
    float* sm, int b, const float* __restrict__ h2,
    const float* __restrict__ enc, const float* __restrict__ encatt,
    const float* __restrict__ Wa1, const float* __restrict__ Wa2,
    const float* __restrict__ ba2,
    bf* __restrict__ ctxh, bf* __restrict__ ctxl)
{
    __syncthreads();
    float* sh_h  = sm;
    float* sh_hp = sm + 512;
    float* sh_s  = sm + 544;
    int tid = threadIdx.x;

    for (int k = tid; k < DD; k += NT) sh_h[k] = h2[(size_t)b * DD + k];
    __syncthreads();

    int warp = tid >> 5, lane = tid & 31;
    for (int j = warp; j < ATTH; j += 16) {
        const float* w = Wa1 + (size_t)j * (EENC + DD) + EENC;
        float s = 0.f;
        for (int k = lane; k < DD; k += 32) s += sh_h[k] * w[k];
#pragma unroll
        for (int o = 16; o; o >>= 1) s += __shfl_xor_sync(0xFFFFFFFFu, s, o);
        if (lane == 0) sh_hp[j] = s;
    }
    __syncthreads();

    if (tid < LL) {
        const float* ea = encatt + ((size_t)b * LL + tid) * ATTH;
        float s = 0.f;
#pragma unroll
        for (int j = 0; j < ATTH; j++) {
            float v = ea[j] + sh_hp[j];
            v = v > 0.f ? v : 0.f;
            s += v * Wa2[j];
        }
        sh_s[tid] = tanhf(s + ba2[0]);
    }
    __syncthreads();

    if (tid == 0) {
        float m = sh_s[0];
        for (int l = 1; l < LL; l++) m = fmaxf(m, sh_s[l]);
        float sum = 0.f;
        for (int l = 0; l < LL; l++) { float e = expf(sh_s[l] - m); sh_s[l] = e; sum += e; }
        float inv = 1.f / sum;
        for (int l = 0; l < LL; l++) sh_s[l] *= inv;
    }
    __syncthreads();

    const float* eb = enc + (size_t)b * LL * EENC;
    for (int k = tid; k < EENC; k += NT) {
        float s = 0.f;
#pragma unroll 8
        for (int l = 0; l < LL; l++) s += sh_s[l] * eb[(size_t)l * EENC + k];
        bf vh, vl; split_bf(s, vh, vl);
        ctxh[(size_t)b * EENC + k] = vh;
        ctxl[(size_t)b * EENC + k] = vl;
    }
}

// ---------------- kernel params ----------------
struct Params {
    const int* act;
    const float* enc;
    const float* enc_h;
    const float* enc_c;
    const float* embW;
    const float* Wc;  const float* bc;
    const float* Wih[3]; const float* Whh[3];
    const float* bih[3]; const float* bhh[3];
    const float* Wa1; const float* ba1;
    const float* Wa2; const float* ba2;
    const float* Wl1; const float* bl1;
    const float* Wl2; const float* bl2;
    float* out;
};

// ---------------- persistent mega-kernel ----------------
__global__ void __launch_bounds__(NT, 1) decoder_kernel(Params p)
{
    extern __shared__ __align__(16) bf stg[];
    float* smf = (float*)stg;
    const int nb  = gridDim.x;
    const int bid = blockIdx.x;
    const int tid = threadIdx.x;
    const int gt = bid * NT + tid, gs = nb * NT;

    // ---- phase 0: setup ----
    for (int idx = gt; idx < BB * DD; idx += gs) {
        float h = p.enc_h[idx], c = p.enc_c[idx];
        bf vh, vl; split_bf(h, vh, vl);
#pragma unroll
        for (int cc = 0; cc < 3; cc++) {
            g_hf[cc][0][idx] = h;
            g_hh[cc][0][idx] = vh; g_hl[cc][0][idx] = vl;
            g_c[cc][idx] = c;
        }
        g_ctx_h[idx] = __float2bfloat16(0.f);
        g_ctx_l[idx] = __float2bfloat16(0.f);
    }
    // eseq: teacher-forcing embeddings, split
    for (int i4 = gt; i4 < TT * BB * EMBW / 4; i4 += gs) {
        int row = i4 >> 5;
        int kq  = i4 & 31;
        int t = row >> 8;
        int b = row & 255;
        float4 v = make_float4(0.f, 0.f, 0.f, 0.f);
        if (t > 0) {
            int a = p.act[b * TT + t - 1];
            v = *(const float4*)(p.embW + (size_t)a * EMBW + kq * 4);
        }
        size_t base = (size_t)row * EMBW + kq * 4;
        bf vh, vl;
        split_bf(v.x, vh, vl); g_eseq_h[base + 0] = vh; g_eseq_l[base + 0] = vl;
        split_bf(v.y, vh, vl); g_eseq_h[base + 1] = vh; g_eseq_l[base + 1] = vl;
        split_bf(v.z, vh, vl); g_eseq_h[base + 2] = vh; g_eseq_l[base + 2] = vl;
        split_bf(v.w, vh, vl); g_eseq_h[base + 3] = vh; g_eseq_l[base + 3] = vl;
    }
    // weight splitting
    for (int i = gt; i < DD * (EMBW + EENC); i += gs) {
        bf vh, vl; split_bf(p.Wc[i], vh, vl);
        g_Wc_h[i] = vh; g_Wc_l[i] = vl;
    }
#pragma unroll
    for (int cc = 0; cc < 3; cc++) {
        for (int i = gt; i < 4 * DD * DD; i += gs) {
            bf vh, vl;
            split_bf(p.Wih[cc][i], vh, vl); g_Wih_h[cc][i] = vh; g_Wih_l[cc][i] = vl;
            split_bf(p.Whh[cc][i], vh, vl); g_Whh_h[cc][i] = vh; g_Whh_l[cc][i] = vl;
        }
    }
    for (int i = gt; i < DD * (DD + EENC); i += gs) {
        bf vh, vl; split_bf(p.Wl1[i], vh, vl);
        g_Wl1_h[i] = vh; g_Wl1_l[i] = vl;
    }
    for (int i = gt; i < AA * DD; i += gs) {
        bf vh, vl; split_bf(p.Wl2[i], vh, vl);
        g_Wl2_h[i] = vh; g_Wl2_l[i] = vl;
    }
    // encatt (encoder side of attention MLP, fp32, time-invariant)
    {
        int lane = tid & 31;
        int gw0 = gt >> 5;
        for (int gw = gw0; gw < BB * LL; gw += gs >> 5) {
            const float* er = p.enc + (size_t)gw * EENC;
            float r[16];
#pragma unroll
            for (int i = 0; i < 16; i++) r[i] = er[lane + 32 * i];
            for (int j = 0; j < ATTH; j++) {
                const float* w = p.Wa1 + (size_t)j * (EENC + DD);
                float s = 0.f;
#pragma unroll
                for (int i = 0; i < 16; i++) s += r[i] * w[lane + 32 * i];
#pragma unroll
                for (int o = 16; o; o >>= 1) s += __shfl_xor_sync(0xFFFFFFFFu, s, o);
                if (lane == 0) g_encatt[(size_t)gw * ATTH + j] = s + p.ba1[j];
            }
        }
    }
    gsync(nb);

    // ---- att for t=0: [e_0 | ctx0] @ Wc^T + bc ----
    for (int tile = bid; tile < 32; tile += nb)
        mm_tile(stg, tile, g_eseq_h, g_eseq_l, EMBW, g_ctx_h, g_ctx_l, EENC,
                g_Wc_h, g_Wc_l, EMBW + EENC, DD, p.bc, 0,
                (float*)0, 0, g_att_h, g_att_l, DD);
    gsync(nb);

    // ---- main loop ----
    for (int t = 0; t < TT; t++) {
        const int cur = t & 1, nxt = cur ^ 1;

        const bf* xinh = g_att_h;
        const bf* xinl = g_att_l;
#pragma unroll 1
        for (int cell = 0; cell < 3; cell++) {
            for (int tile = bid; tile < 128; tile += nb)
                lstm_mma(stg, tile, xinh, xinl,
                         g_hh[cell][cur], g_hl[cell][cur],
                         g_Wih_h[cell], g_Wih_l[cell],
                         g_Whh_h[cell], g_Whh_l[cell],
                         p.bih[cell], p.bhh[cell],
                         g_hf[cell][nxt], g_hh[cell][nxt], g_hl[cell][nxt],
                         g_c[cell]);
            gsync(nb);
            xinh = g_hh[cell][nxt];
            xinl = g_hl[cell][nxt];
        }

        for (int b = bid; b < BB; b += nb)
            attention_row(smf, b, g_hf[2][nxt], p.enc, g_encatt,
                          p.Wa1, p.Wa2, p.ba2, g_ctx_h, g_ctx_l);
        gsync(nb);

        // action head L1: relu([h2|ctx] @ Wl1^T + bl1) -> act1 (hi/lo)
        for (int tile = bid; tile < 32; tile += nb)
            mm_tile(stg, tile, g_hh[2][nxt], g_hl[2][nxt], DD,
                    g_ctx_h, g_ctx_l, EENC,
                    g_Wl1_h, g_Wl1_l, DD + EENC, DD, p.bl1, 1,
                    (float*)0, 0, g_act1_h, g_act1_l, DD);
        gsync(nb);

        // combined: logits(t) -> out  AND  att(t+1) (independent)
        const int ntot = 12 + ((t + 1 < TT) ? 32 : 0);
        for (int u = bid; u < ntot; u += nb) {
            if (u < 12)
                mm_tile(stg, u, g_act1_h, g_act1_l, DD, (const bf*)0, (const bf*)0, 0,
                        g_Wl2_h, g_Wl2_l, DD, AA, p.bl2, 0,
                        p.out + (size_t)t * AA, (size_t)TT * AA,
                        (bf*)0, (bf*)0, 0);
            else
                mm_tile(stg, u - 12,
                        g_eseq_h + (size_t)(t + 1) * BB * EMBW,
                        g_eseq_l + (size_t)(t + 1) * BB * EMBW, EMBW,
                        g_ctx_h, g_ctx_l, EENC,
                        g_Wc_h, g_Wc_l, EMBW + EENC, DD, p.bc, 0,
                        (float*)0, 0, g_att_h, g_att_l, DD);
        }
        gsync(nb);
    }
}

// ---------------- host ----------------
extern "C" void kernel_launch(void* const* d_in, const int* in_sizes, int n_in,
                              void* d_out, int out_size)
{
    Params p;
    p.act    = (const int*)  d_in[0];
    p.enc    = (const float*)d_in[1];
    p.enc_h  = (const float*)d_in[2];
    p.enc_c  = (const float*)d_in[3];
    p.embW   = (const float*)d_in[4];
    p.Wc     = (const float*)d_in[5];
    p.bc     = (const float*)d_in[6];
    p.Wih[0] = (const float*)d_in[7];  p.Whh[0] = (const float*)d_in[8];
    p.bih[0] = (const float*)d_in[9];  p.bhh[0] = (const float*)d_in[10];
    p.Wih[1] = (const float*)d_in[11]; p.Whh[1] = (const float*)d_in[12];
    p.bih[1] = (const float*)d_in[13]; p.bhh[1] = (const float*)d_in[14];
    p.Wih[2] = (const float*)d_in[15]; p.Whh[2] = (const float*)d_in[16];
    p.bih[2] = (const float*)d_in[17]; p.bhh[2] = (const float*)d_in[18];
    p.Wa1 = (const float*)d_in[19]; p.ba1 = (const float*)d_in[20];
    p.Wa2 = (const float*)d_in[21]; p.ba2 = (const float*)d_in[22];
    p.Wl1 = (const float*)d_in[23]; p.bl1 = (const float*)d_in[24];
    p.Wl2 = (const float*)d_in[25]; p.bl2 = (const float*)d_in[26];
    p.out = (float*)d_out;

    int dev = 0;
    cudaGetDevice(&dev);
    int nsm = 0;
    cudaDeviceGetAttribute(&nsm, cudaDevAttrMultiProcessorCount, dev);
    if (nsm <= 0) nsm = 148;

    cudaFuncSetAttribute(decoder_kernel,
                         cudaFuncAttributeMaxDynamicSharedMemorySize, SMEM_BYTES);
    decoder_kernel<<<nsm, NT, SMEM_BYTES>>>(p);
}

// round 7
// speedup vs baseline: 2.9299x; 1.4180x over previous
#include <cuda_runtime.h>
#include <cuda_bf16.h>
#include <math.h>

#define BB   256
#define TT   128
#define LL   64
#define EENC 512
#define DD   512
#define EMBW 128
#define AA   129
#define ATTH 20

#define NT   512

#define PIT    40                  // smem row pitch in bf16 (80B, ldsm conflict-free)
#define MATSZ  (64 * PIT)          // one 64x32 staged matrix (2560 elems)
#define BUFE   (4 * MATSZ)         // Ahi, Alo, Whi, Wlo per stage (10240 elems)
#define RING   4
#define SMEM_BYTES (RING * BUFE * 2)   // 81920 B

typedef unsigned int u32;
typedef __nv_bfloat16 bf;

// ---------------- device scratch (static, no allocs) ----------------
__device__ __align__(16) bf    g_eseq_h[TT * BB * EMBW];
__device__ __align__(16) bf    g_eseq_l[TT * BB * EMBW];
__device__ __align__(16) float g_encatt[BB * LL * ATTH];
__device__ __align__(16) bf    g_att_h[BB * DD],  g_att_l[BB * DD];
__device__ __align__(16) float g_hf[3][2][BB * DD];
__device__ __align__(16) bf    g_hh[3][2][BB * DD], g_hl[3][2][BB * DD];
__device__ __align__(16) float g_c[3][BB * DD];
__device__ __align__(16) bf    g_ctx_h[BB * EENC], g_ctx_l[BB * EENC];
__device__ __align__(16) bf    g_act1_h[BB * DD],  g_act1_l[BB * DD];

__device__ __align__(16) bf g_Wc_h[DD * (EMBW + EENC)],  g_Wc_l[DD * (EMBW + EENC)];
__device__ __align__(16) bf g_Wih_h[3][4 * DD * DD], g_Wih_l[3][4 * DD * DD];
__device__ __align__(16) bf g_Whh_h[3][4 * DD * DD], g_Whh_l[3][4 * DD * DD];
__device__ __align__(16) bf g_Wl1_h[DD * (DD + EENC)], g_Wl1_l[DD * (DD + EENC)];
__device__ __align__(16) bf g_Wl2_h[AA * DD], g_Wl2_l[AA * DD];

__device__ unsigned int g_bar_count = 0;
__device__ unsigned int g_bar_gen   = 0;

// ---------------- helpers ----------------
__device__ __forceinline__ void split_bf(float x, bf& h, bf& l) {
    h = __float2bfloat16(x);
    l = __float2bfloat16(x - __bfloat162float(h));
}
__device__ __forceinline__ u32 sptr(const void* p) {
    return (u32)__cvta_generic_to_shared(p);
}
__device__ __forceinline__ void ldsm4(u32* r, u32 a) {
    asm volatile("ldmatrix.sync.aligned.m8n8.x4.shared.b16 {%0,%1,%2,%3}, [%4];"
                 : "=r"(r[0]), "=r"(r[1]), "=r"(r[2]), "=r"(r[3]) : "r"(a));
}
__device__ __forceinline__ void mma16816(float* d, const u32* a, const u32* b) {
    asm volatile(
        "mma.sync.aligned.m16n8k16.row.col.f32.bf16.bf16.f32 "
        "{%0,%1,%2,%3},{%4,%5,%6,%7},{%8,%9},{%0,%1,%2,%3};"
        : "+f"(d[0]), "+f"(d[1]), "+f"(d[2]), "+f"(d[3])
        : "r"(a[0]), "r"(a[1]), "r"(a[2]), "r"(a[3]), "r"(b[0]), "r"(b[1]));
}
__device__ __forceinline__ void cpa(u32 dst, const void* src, int sz) {
    asm volatile("cp.async.cg.shared.global [%0], [%1], 16, %2;"
                 :: "r"(dst), "l"(src), "r"(sz));
}
__device__ __forceinline__ void cp_commit() {
    asm volatile("cp.async.commit_group;" ::: "memory");
}
__device__ __forceinline__ void cp_wait2() {
    asm volatile("cp.async.wait_group 2;" ::: "memory");
}
#define HBAR(id) asm volatile("bar.sync %0, 256;" :: "r"(id) : "memory")

// ---------------- launch-reentrant grid barrier ----------------
__device__ __forceinline__ void gsync(int nb) {
    __syncthreads();
    if (threadIdx.x == 0) {
        __threadfence();
        unsigned int gen = *(volatile unsigned int*)&g_bar_gen;
        if (atomicAdd(&g_bar_count, 1u) == (unsigned int)(nb - 1)) {
            g_bar_count = 0;
            __threadfence();
            atomicAdd(&g_bar_gen, 1u);
        } else {
            while (*(volatile unsigned int*)&g_bar_gen == gen) { }
        }
        __threadfence();
    }
    __syncthreads();
}

// ---------------- stage compute (shared by both tile kernels) ----------------
__device__ __forceinline__ void stage_mma(bf* buf, int wm, int wn, int lane,
                                          float acc[2][4]) {
#pragma unroll
    for (int q = 0; q < 2; q++) {
        u32 ah[4], al[4], bh[4], bl[4];
        u32 abase = sptr(buf + (wm * 16 + (lane & 15)) * PIT
                             + q * 16 + ((lane >> 4) & 1) * 8);
        ldsm4(ah, abase);
        ldsm4(al, abase + MATSZ * 2);
        u32 bbase = sptr(buf + 2 * MATSZ
                             + (wn * 16 + (lane & 7) + ((lane >> 4) & 1) * 8) * PIT
                             + q * 16 + ((lane >> 3) & 1) * 8);
        ldsm4(bh, bbase);
        ldsm4(bl, bbase + MATSZ * 2);
        mma16816(acc[0], ah, bh + 0);
        mma16816(acc[1], ah, bh + 2);
        mma16816(acc[0], ah, bl + 0);
        mma16816(acc[1], ah, bl + 2);
        mma16816(acc[0], al, bh + 0);
        mma16816(acc[1], al, bh + 2);
    }
}

// ---------------- generic 64x64 mma tile: C = [A1|A2] @ W^T + bias ----------------
__device__ __forceinline__ void mm_tile(
    bf* stg, int tile,
    const bf* __restrict__ A1h, const bf* __restrict__ A1l, int K1,
    const bf* __restrict__ A2h, const bf* __restrict__ A2l, int K2,
    const bf* __restrict__ Wh,  const bf* __restrict__ Wl, int ldw, int N,
    const float* __restrict__ bias, int relu,
    float* __restrict__ Cf, size_t ldc,
    bf* __restrict__ Ch, bf* __restrict__ Cl, int ldcb)
{
    __syncthreads();
    const int tid = threadIdx.x;
    const int lane = tid & 31, warp = tid >> 5;
    const int wm = warp >> 2, wn = warp & 3;
    const int ntN = (N + 63) >> 6;
    const int m0 = (tile / ntN) * 64, n0 = (tile % ntN) * 64;
    const int S = (K1 + K2) >> 5;

    const int smat = tid >> 8;             // 0=hi, 1=lo
    const int srow = (tid >> 2) & 63;
    const int schk = tid & 3;              // 16B chunk in 32-col row
    const int wrow = n0 + srow;
    const int wsz  = (wrow < N) ? 16 : 0;
    const int wr_c = (wrow < N) ? wrow : 0;   // clamped source row

    float acc[2][4] = {};

    auto issue = [&](int s) {
        int kb = s << 5;
        const bf* Ap; int lda, ka;
        if (kb < K1) { Ap = smat ? A1l : A1h; lda = K1; ka = kb; }
        else         { Ap = smat ? A2l : A2h; lda = K2; ka = kb - K1; }
        bf* buf = stg + (s & 3) * BUFE;
        u32 da = sptr(buf + smat * MATSZ + srow * PIT + schk * 8);
        u32 dw = sptr(buf + (2 + smat) * MATSZ + srow * PIT + schk * 8);
        cpa(da, Ap + (size_t)(m0 + srow) * lda + ka + schk * 8, 16);
        const bf* Wp = smat ? Wl : Wh;
        cpa(dw, Wp + (size_t)wr_c * ldw + kb + schk * 8, wsz);
    };

    if (0 < S) issue(0);
    cp_commit();
    if (1 < S) issue(1);
    cp_commit();
    if (2 < S) issue(2);
    cp_commit();

    for (int s = 0; s < S; s++) {
        cp_wait2();
        __syncthreads();
        if (s + 3 < S) issue(s + 3);
        cp_commit();
        stage_mma(stg + (s & 3) * BUFE, wm, wn, lane, acc);
    }

    // epilogue (register-only + gmem)
#pragma unroll
    for (int bb = 0; bb < 2; bb++) {
        int nc = n0 + wn * 16 + bb * 8 + (lane & 3) * 2;
        int r0 = m0 + wm * 16 + (lane >> 2);
#pragma unroll
        for (int hf = 0; hf < 2; hf++) {
            int r = r0 + hf * 8;
#pragma unroll
            for (int j = 0; j < 2; j++) {
                int n = nc + j;
                if (n < N) {
                    float v = acc[bb][hf * 2 + j] + bias[n];
                    if (relu) v = fmaxf(v, 0.f);
                    if (Cf) Cf[(size_t)r * ldc + n] = v;
                    if (Ch) {
                        bf vh, vl; split_bf(v, vh, vl);
                        Ch[(size_t)r * ldcb + n] = vh;
                        Cl[(size_t)r * ldcb + n] = vl;
                    }
                }
            }
        }
    }
}

// ---------------- LSTM 64x64 mma tile: gate remap + fused pointwise ----------
__device__ __forceinline__ void lstm_mma(
    bf* stg, int tile,
    const bf* __restrict__ xh, const bf* __restrict__ xl,
    const bf* __restrict__ hhx, const bf* __restrict__ hlx,
    const bf* __restrict__ Wihh, const bf* __restrict__ Wihl,
    const bf* __restrict__ Whhh, const bf* __restrict__ Whhl,
    const float* __restrict__ bih, const float* __restrict__ bhh,
    float* __restrict__ houtf, bf* __restrict__ houth, bf* __restrict__ houtl,
    float* __restrict__ cbuf)
{
    __syncthreads();
    const int tid = threadIdx.x;
    const int lane = tid & 31, warp = tid >> 5;
    const int wm = warp >> 2, wn = warp & 3;
    const int m0 = (tile >> 5) * 64;
    const int d0 = (tile & 31) * 16;

    const int smat = tid >> 8;
    const int srow = (tid >> 2) & 63;
    const int schk = tid & 3;
    const int wrow = ((srow >> 4) << 9) + d0 + (srow & 15);   // gate*512 + d

    float acc[2][4] = {};

    auto issue = [&](int s) {
        const bf* Ap = (s < 16) ? (smat ? xl : xh) : (smat ? hlx : hhx);
        const bf* Wp = (s < 16) ? (smat ? Wihl : Wihh) : (smat ? Whhl : Whhh);
        int kb = (s & 15) * 32;
        bf* buf = stg + (s & 3) * BUFE;
        u32 da = sptr(buf + smat * MATSZ + srow * PIT + schk * 8);
        u32 dw = sptr(buf + (2 + smat) * MATSZ + srow * PIT + schk * 8);
        cpa(da, Ap + (size_t)(m0 + srow) * 512 + kb + schk * 8, 16);
        cpa(dw, Wp + (size_t)wrow * 512 + kb + schk * 8, 16);
    };

    issue(0); cp_commit();
    issue(1); cp_commit();
    issue(2); cp_commit();

    for (int s = 0; s < 32; s++) {
        cp_wait2();
        __syncthreads();
        if (s + 3 < 32) issue(s + 3);
        cp_commit();
        stage_mma(stg + (s & 3) * BUFE, wm, wn, lane, acc);
    }

    // dump C frags to smem G[64][68] (slot 0 area; last compute read slot 3)
    float* G = (float*)stg;
#pragma unroll
    for (int bb = 0; bb < 2; bb++) {
        int c = wn * 16 + bb * 8 + (lane & 3) * 2;
        int r0 = wm * 16 + (lane >> 2);
        *(float2*)(G + r0 * 68 + c)       = make_float2(acc[bb][0], acc[bb][1]);
        *(float2*)(G + (r0 + 8) * 68 + c) = make_float2(acc[bb][2], acc[bb][3]);
    }
    __syncthreads();

    for (int e = tid; e < 1024; e += NT) {
        int m = e & 63, dp = e >> 6;
        int d = d0 + dp;
        const float* Gm = G + m * 68;
        float gi = Gm[dp]      + bih[d]        + bhh[d];
        float gf = Gm[16 + dp] + bih[512 + d]  + bhh[512 + d];
        float gg = Gm[32 + dp] + bih[1024 + d] + bhh[1024 + d];
        float go = Gm[48 + dp] + bih[1536 + d] + bhh[1536 + d];
        size_t idx = (size_t)(m0 + m) * 512 + d;
        float si = 1.f / (1.f + expf(-gi));
        float sf = 1.f / (1.f + expf(-gf));
        float so = 1.f / (1.f + expf(-go));
        float cn = sf * cbuf[idx] + si * tanhf(gg);
        cbuf[idx] = cn;
        float hn = so * tanhf(cn);
        houtf[idx] = hn;
        bf vh, vl; split_bf(hn, vh, vl);
        houth[idx] = vh;
        houtl[idx] = vl;
    }
}

// ---------------- kernel params ----------------
struct Params {
    const int* act;
    const float* enc;
    const float* enc_h;
    const float* enc_c;
    const float* embW;
    const float* Wc;  const float* bc;
    const float* Wih[3]; const float* Whh[3];
    const float* bih[3]; const float* bhh[3];
    const float* Wa1; const float* ba1;
    const float* Wa2; const float* ba2;
    const float* Wl1; const float* bl1;
    const float* Wl2; const float* bl2;
    float* out;
};

// ---------------- persistent mega-kernel ----------------
__global__ void __launch_bounds__(NT, 1) decoder_kernel(Params p)
{
    extern __shared__ __align__(16) bf stg[];
    const int nb  = gridDim.x;
    const int bid = blockIdx.x;
    const int tid = threadIdx.x;
    const int gt = bid * NT + tid, gs = nb * NT;

    // ---- phase 0: setup ----
    for (int idx = gt; idx < BB * DD; idx += gs) {
        float h = p.enc_h[idx], c = p.enc_c[idx];
        bf vh, vl; split_bf(h, vh, vl);
#pragma unroll
        for (int cc = 0; cc < 3; cc++) {
            g_hf[cc][0][idx] = h;
            g_hh[cc][0][idx] = vh; g_hl[cc][0][idx] = vl;
            g_c[cc][idx] = c;
        }
        g_ctx_h[idx] = __float2bfloat16(0.f);
        g_ctx_l[idx] = __float2bfloat16(0.f);
    }
    for (int i4 = gt; i4 < TT * BB * EMBW / 4; i4 += gs) {
        int row = i4 >> 5;
        int kq  = i4 & 31;
        int t = row >> 8;
        int b = row & 255;
        float4 v = make_float4(0.f, 0.f, 0.f, 0.f);
        if (t > 0) {
            int a = p.act[b * TT + t - 1];
            v = *(const float4*)(p.embW + (size_t)a * EMBW + kq * 4);
        }
        size_t base = (size_t)row * EMBW + kq * 4;
        bf vh, vl;
        split_bf(v.x, vh, vl); g_eseq_h[base + 0] = vh; g_eseq_l[base + 0] = vl;
        split_bf(v.y, vh, vl); g_eseq_h[base + 1] = vh; g_eseq_l[base + 1] = vl;
        split_bf(v.z, vh, vl); g_eseq_h[base + 2] = vh; g_eseq_l[base + 2] = vl;
        split_bf(v.w, vh, vl); g_eseq_h[base + 3] = vh; g_eseq_l[base + 3] = vl;
    }
    for (int i = gt; i < DD * (EMBW + EENC); i += gs) {
        bf vh, vl; split_bf(p.Wc[i], vh, vl);
        g_Wc_h[i] = vh; g_Wc_l[i] = vl;
    }
#pragma unroll
    for (int cc = 0; cc < 3; cc++) {
        for (int i = gt; i < 4 * DD * DD; i += gs) {
            bf vh, vl;
            split_bf(p.Wih[cc][i], vh, vl); g_Wih_h[cc][i] = vh; g_Wih_l[cc][i] = vl;
            split_bf(p.Whh[cc][i], vh, vl); g_Whh_h[cc][i] = vh; g_Whh_l[cc][i] = vl;
        }
    }
    for (int i = gt; i < DD * (DD + EENC); i += gs) {
        bf vh, vl; split_bf(p.Wl1[i], vh, vl);
        g_Wl1_h[i] = vh; g_Wl1_l[i] = vl;
    }
    for (int i = gt; i < AA * DD; i += gs) {
        bf vh, vl; split_bf(p.Wl2[i], vh, vl);
        g_Wl2_h[i] = vh; g_Wl2_l[i] = vl;
    }
    {
        int lane = tid & 31;
        int gw0 = gt >> 5;
        for (int gw = gw0; gw < BB * LL; gw += gs >> 5) {
            const float* er = p.enc + (size_t)gw * EENC;
            float r[16];
#pragma unroll
            for (int i = 0; i < 16; i++) r[i] = er[lane + 32 * i];
            for (int j = 0; j < ATTH; j++) {
                const float* w = p.Wa1 + (size_t)j * (EENC + DD);
                float s = 0.f;
#pragma unroll
                for (int i = 0; i < 16; i++) s += r[i] * w[lane + 32 * i];
#pragma unroll
                for (int o = 16; o; o >>= 1) s += __shfl_xor_sync(0xFFFFFFFFu, s, o);
                if (lane == 0) g_encatt[(size_t)gw * ATTH + j] = s + p.ba1[j];
            }
        }
    }
    gsync(nb);

    // ---- att for t=0 ----
    for (int u = bid; u < 32; u += nb)
        mm_tile(stg, u, g_eseq_h, g_eseq_l, EMBW, g_ctx_h, g_ctx_l, EENC,
                g_Wc_h, g_Wc_l, EMBW + EENC, DD, p.bc, 0,
                (float*)0, 0, g_att_h, g_att_l, DD);
    gsync(nb);

    // ---- main loop ----
    for (int t = 0; t < TT; t++) {
        const int cur = t & 1, nxt = cur ^ 1;

        // Phase A: LSTM cell0 (+ logits of t-1, independent)
        {
            const int ntA = 128 + (t > 0 ? 12 : 0);
            for (int u = bid; u < ntA; u += nb) {
                if (u < 128)
                    lstm_mma(stg, u, g_att_h, g_att_l,
                             g_hh[0][cur], g_hl[0][cur],
                             g_Wih_h[0], g_Wih_l[0], g_Whh_h[0], g_Whh_l[0],
                             p.bih[0], p.bhh[0],
                             g_hf[0][nxt], g_hh[0][nxt], g_hl[0][nxt], g_c[0]);
                else
                    mm_tile(stg, u - 128, g_act1_h, g_act1_l, DD,
                            (const bf*)0, (const bf*)0, 0,
                            g_Wl2_h, g_Wl2_l, DD, AA, p.bl2, 0,
                            p.out + (size_t)(t - 1) * AA, (size_t)TT * AA,
                            (bf*)0, (bf*)0, 0);
            }
            gsync(nb);
        }

        // Phases B, C: cells 1, 2
        for (int cell = 1; cell < 3; cell++) {
            for (int u = bid; u < 128; u += nb)
                lstm_mma(stg, u, g_hh[cell - 1][nxt], g_hl[cell - 1][nxt],
                         g_hh[cell][cur], g_hl[cell][cur],
                         g_Wih_h[cell], g_Wih_l[cell],
                         g_Whh_h[cell], g_Whh_l[cell],
                         p.bih[cell], p.bhh[cell],
                         g_hf[cell][nxt], g_hh[cell][nxt], g_hl[cell][nxt],
                         g_c[cell]);
            gsync(nb);
        }

        // Phase D: attention, 2 rows/block via half-block barriers
        __syncthreads();
        {
            const int half = tid >> 8;
            const int htid = tid & 255;
            const int barid = 1 + half;
            float* smf = (float*)stg + half * 2048;
            const int warp8 = htid >> 5, lane = htid & 31;
            for (int b = bid * 2 + half; b < BB; b += nb * 2) {
                float* sh_h  = smf;
                float* sh_hp = smf + 512;
                float* sh_s  = smf + 544;
                const float* h2 = g_hf[2][nxt];
                for (int k = htid; k < DD; k += 256) sh_h[k] = h2[(size_t)b * DD + k];
                HBAR(barid);
                for (int j = warp8; j < ATTH; j += 8) {
                    const float* w = p.Wa1 + (size_t)j * (EENC + DD) + EENC;
                    float s = 0.f;
                    for (int k = lane; k < DD; k += 32) s += sh_h[k] * w[k];
#pragma unroll
                    for (int o = 16; o; o >>= 1) s += __shfl_xor_sync(0xFFFFFFFFu, s, o);
                    if (lane == 0) sh_hp[j] = s;
                }
                HBAR(barid);
                if (htid < LL) {
                    const float* ea = g_encatt + ((size_t)b * LL + htid) * ATTH;
                    float s = 0.f;
#pragma unroll
                    for (int j = 0; j < ATTH; j++) {
                        float v = ea[j] + sh_hp[j];
                        v = v > 0.f ? v : 0.f;
                        s += v * p.Wa2[j];
                    }
                    sh_s[htid] = tanhf(s + p.ba2[0]);
                }
                HBAR(barid);
                if (warp8 == 0) {
                    float v0 = sh_s[lane], v1 = sh_s[lane + 32];
                    float m = fmaxf(v0, v1);
#pragma unroll
                    for (int o = 16; o; o >>= 1) m = fmaxf(m, __shfl_xor_sync(0xFFFFFFFFu, m, o));
                    float e0 = expf(v0 - m), e1 = expf(v1 - m);
                    float sum = e0 + e1;
#pragma unroll
                    for (int o = 16; o; o >>= 1) sum += __shfl_xor_sync(0xFFFFFFFFu, sum, o);
                    float inv = 1.f / sum;
                    sh_s[lane] = e0 * inv;
                    sh_s[lane + 32] = e1 * inv;
                }
                HBAR(barid);
                const float* eb = p.enc + (size_t)b * LL * EENC;
                for (int k = htid; k < EENC; k += 256) {
                    float s = 0.f;
#pragma unroll 8
                    for (int l = 0; l < LL; l++) s += sh_s[l] * eb[(size_t)l * EENC + k];
                    bf vh, vl; split_bf(s, vh, vl);
                    g_ctx_h[(size_t)b * EENC + k] = vh;
                    g_ctx_l[(size_t)b * EENC + k] = vl;
                }
            }
        }
        gsync(nb);

        // Phase E: Wl1 (needs ctx,h2) + att(t+1) (needs ctx) — independent
        {
            const int ntE = 32 + ((t + 1 < TT) ? 32 : 0);
            for (int u = bid; u < ntE; u += nb) {
                if (u < 32)
                    mm_tile(stg, u, g_hh[2][nxt], g_hl[2][nxt], DD,
                            g_ctx_h, g_ctx_l, EENC,
                            g_Wl1_h, g_Wl1_l, DD + EENC, DD, p.bl1, 1,
                            (float*)0, 0, g_act1_h, g_act1_l, DD);
                else
                    mm_tile(stg, u - 32,
                            g_eseq_h + (size_t)(t + 1) * BB * EMBW,
                            g_eseq_l + (size_t)(t + 1) * BB * EMBW, EMBW,
                            g_ctx_h, g_ctx_l, EENC,
                            g_Wc_h, g_Wc_l, EMBW + EENC, DD, p.bc, 0,
                            (float*)0, 0, g_att_h, g_att_l, DD);
            }
            gsync(nb);
        }
    }

    // final logits (t = TT-1)
    for (int u = bid; u < 12; u += nb)
        mm_tile(stg, u, g_act1_h, g_act1_l, DD, (const bf*)0, (const bf*)0, 0,
                g_Wl2_h, g_Wl2_l, DD, AA, p.bl2, 0,
                p.out + (size_t)(TT - 1) * AA, (size_t)TT * AA,
                (bf*)0, (bf*)0, 0);
}

// ---------------- host ----------------
extern "C" void kernel_launch(void* const* d_in, const int* in_sizes, int n_in,
                              void* d_out, int out_size)
{
    Params p;
    p.act    = (const int*)  d_in[0];
    p.enc    = (const float*)d_in[1];
    p.enc_h  = (const float*)d_in[2];
    p.enc_c  = (const float*)d_in[3];
    p.embW   = (const float*)d_in[4];
    p.Wc     = (const float*)d_in[5];
    p.bc     = (const float*)d_in[6];
    p.Wih[0] = (const float*)d_in[7];  p.Whh[0] = (const float*)d_in[8];
    p.bih[0] = (const float*)d_in[9];  p.bhh[0] = (const float*)d_in[10];
    p.Wih[1] = (const float*)d_in[11]; p.Whh[1] = (const float*)d_in[12];
    p.bih[1] = (const float*)d_in[13]; p.bhh[1] = (const float*)d_in[14];
    p.Wih[2] = (const float*)d_in[15]; p.Whh[2] = (const float*)d_in[16];
    p.bih[2] = (const float*)d_in[17]; p.bhh[2] = (const float*)d_in[18];
    p.Wa1 = (const float*)d_in[19]; p.ba1 = (const float*)d_in[20];
    p.Wa2 = (const float*)d_in[21]; p.ba2 = (const float*)d_in[22];
    p.Wl1 = (const float*)d_in[23]; p.bl1 = (const float*)d_in[24];
    p.Wl2 = (const float*)d_in[25]; p.bl2 = (const float*)d_in[26];
    p.out = (float*)d_out;

    int dev = 0;
    cudaGetDevice(&dev);
    int nsm = 0;
    cudaDeviceGetAttribute(&nsm, cudaDevAttrMultiProcessorCount, dev);
    if (nsm <= 0) nsm = 148;

    cudaFuncSetAttribute(decoder_kernel,
                         cudaFuncAttributeMaxDynamicSharedMemorySize, SMEM_BYTES);
    decoder_kernel<<<nsm, NT, SMEM_BYTES>>>(p);
}